// round 12
// baseline (speedup 1.0000x reference)
#include <cuda_runtime.h>
#include <cuda_bf16.h>
#include <cuda_fp16.h>
#include <cstdint>

// Problem constants
#define NN 50000
#define EE 1000000
#define F_IN 256
#define UNITS 128
#define NCLS 40
#define NCLS_PAD 64
#define EPSBN 1e-3f

#define SCAN_B 256
#define NBLK ((NN + SCAN_B - 1) / SCAN_B)   // 196

// ================= mma.sync / cp.async helpers =================
__device__ __forceinline__ uint32_t smem_to_u32(const void* p) {
    uint32_t a;
    asm("{ .reg .u64 t; cvta.to.shared.u64 t, %1; cvt.u32.u64 %0, t; }" : "=r"(a) : "l"(p));
    return a;
}
#define LDSM_X4(r, addr) \
    asm volatile("ldmatrix.sync.aligned.m8n8.x4.shared.b16 {%0,%1,%2,%3}, [%4];" \
        : "=r"((r)[0]), "=r"((r)[1]), "=r"((r)[2]), "=r"((r)[3]) : "r"(addr))
#define LDSM_X2(r, addr) \
    asm volatile("ldmatrix.sync.aligned.m8n8.x2.shared.b16 {%0,%1}, [%2];" \
        : "=r"((r)[0]), "=r"((r)[1]) : "r"(addr))

__device__ __forceinline__ void mma_f16(float* c, const uint32_t* a, const uint32_t* b) {
    asm volatile("mma.sync.aligned.m16n8k16.row.col.f32.f16.f16.f32 "
        "{%0,%1,%2,%3}, {%4,%5,%6,%7}, {%8,%9}, {%0,%1,%2,%3};"
        : "+f"(c[0]), "+f"(c[1]), "+f"(c[2]), "+f"(c[3])
        : "r"(a[0]), "r"(a[1]), "r"(a[2]), "r"(a[3]), "r"(b[0]), "r"(b[1]));
}
__device__ __forceinline__ void cp_async16(uint32_t sa, const void* g, uint32_t pbytes) {
    asm volatile("cp.async.cg.shared.global [%0], [%1], 16, %2;"
                 :: "r"(sa), "l"(g), "r"(pbytes) : "memory");
}
#define CP_COMMIT() asm volatile("cp.async.commit_group;" ::: "memory")
#define CP_WAIT0()  asm volatile("cp.async.wait_group 0;" ::: "memory")
#define CP_WAIT1()  asm volatile("cp.async.wait_group 1;" ::: "memory")

// ================= scratch (static device globals) =================
__device__ __align__(16) float g_deg[NN];
__device__ __align__(16) int   g_cnt[NN];
__device__ __align__(16) int   g_rowptr[NN + 1];
__device__ __align__(16) int   g_bsum[NBLK];
__device__ __align__(16) uint2 g_edge[EE];                 // packed (src, norm_w)
__device__ __align__(16) __half g_hwh[(size_t)NN * 128];   // fp16 gcn-path GEMM output
__device__ __align__(16) float g_acc[(size_t)NN * 128];    // fp32 self path
__device__ __align__(16) __half g_xh[(size_t)NN * F_IN];   // fp16 input features
__device__ __align__(16) __half g_hh[(size_t)NN * 128];    // fp16 layer activations
__device__ __align__(16) __half g_w1h[256 * 256];
__device__ __align__(16) __half g_w2h[256 * 128];
__device__ __align__(16) __half g_w3h[128 * 128];
__device__ __align__(16) float g_b3p[NCLS_PAD];

// ================= CSR build =================
__global__ void zero_dc_kernel() {
    int i = blockIdx.x * blockDim.x + threadIdx.x;
    if (i < NN) { g_deg[i] = 0.f; g_cnt[i] = 0; }
}
__global__ void count_deg_kernel(const int* __restrict__ dst, const float* __restrict__ w, int e) {
    int i = blockIdx.x * blockDim.x + threadIdx.x;
    if (i < e) {
        int d = dst[i];
        atomicAdd(&g_cnt[d], 1);
        atomicAdd(&g_deg[d], w[i]);
    }
}
__global__ void __launch_bounds__(SCAN_B) blocksum_dinv_kernel() {
    __shared__ int sh[SCAN_B];
    int i = blockIdx.x * SCAN_B + threadIdx.x;
    int v = 0;
    if (i < NN) {
        v = g_cnt[i];
        float d = g_deg[i];
        g_deg[i] = (d > 0.f) ? rsqrtf(d) : 0.f;
    }
    sh[threadIdx.x] = v;
    __syncthreads();
    for (int off = SCAN_B / 2; off > 0; off >>= 1) {
        if (threadIdx.x < off) sh[threadIdx.x] += sh[threadIdx.x + off];
        __syncthreads();
    }
    if (threadIdx.x == 0) g_bsum[blockIdx.x] = sh[0];
}
__global__ void __launch_bounds__(SCAN_B) scatter_rowptr_kernel() {
    __shared__ int sh[SCAN_B];
    __shared__ int red[SCAN_B];
    int i = blockIdx.x * SCAN_B + threadIdx.x;
    int t = threadIdx.x;
    int bv = (t < NBLK) ? g_bsum[t] : 0;
    red[t] = (t < blockIdx.x) ? bv : 0;
    sh[t] = bv;
    __syncthreads();
    for (int off = SCAN_B / 2; off > 0; off >>= 1) {
        if (t < off) { red[t] += red[t + off]; sh[t] += sh[t + off]; }
        __syncthreads();
    }
    int boff = red[0];
    int total = sh[0];
    __syncthreads();
    int v = (i < NN) ? g_cnt[i] : 0;
    sh[t] = v;
    __syncthreads();
    for (int off = 1; off < SCAN_B; off <<= 1) {
        int u = (t >= off) ? sh[t - off] : 0;
        __syncthreads();
        sh[t] += u;
        __syncthreads();
    }
    if (i < NN) {
        g_rowptr[i] = boff + sh[t] - v;
        g_cnt[i] = 0;
    }
    if (blockIdx.x == NBLK - 1 && t == 0) g_rowptr[NN] = total;
}
__global__ void fill_kernel(const int* __restrict__ src, const int* __restrict__ dst,
                            const float* __restrict__ w, int e) {
    int i = blockIdx.x * blockDim.x + threadIdx.x;
    if (i >= e) return;
    int s = src[i], d = dst[i];
    int pos = g_rowptr[d] + atomicAdd(&g_cnt[d], 1);
    float nw = g_deg[s] * w[i] * g_deg[d];
    g_edge[pos] = make_uint2((uint32_t)s, __float_as_uint(nw));
}

// ================= prep kernels =================
__global__ void prep_w_kernel(const float* __restrict__ Wg, const float* __restrict__ Ws,
                              int K, int NV, int NHALF, __half* __restrict__ wout) {
    int idx = blockIdx.x * blockDim.x + threadIdx.x;
    int total = 2 * NHALF * K;
    if (idx >= total) return;
    int n = idx / K, k = idx - n * K;
    float v = 0.f;
    if (n < NHALF) { if (n < NV) v = Wg[k * NV + n]; }
    else { int c = n - NHALF; if (c < NV) v = Ws[k * NV + c]; }
    wout[idx] = __float2half_rn(v);
}
__global__ void prep_b3_kernel(const float* __restrict__ b) {
    int i = threadIdx.x;
    if (i < NCLS_PAD) g_b3p[i] = (i < NCLS) ? b[i] : 0.f;
}
__global__ void split_kernel(const float* __restrict__ in, __half* __restrict__ o, int n) {
    int i = blockIdx.x * blockDim.x + threadIdx.x;
    if (i < n) o[i] = __float2half_rn(in[i]);
}

// ================= cp.async double-buffered fp16 GEMM; gcn out fp16 =================
template<int K, int NHALF>
__global__ void __launch_bounds__(256) gcn_gemm_mma(
    const __half* __restrict__ A, const __half* __restrict__ W,
    const float* __restrict__ bias,
    __half* __restrict__ out_gcn, float* __restrict__ out_self, int nrows)
{
    constexpr int BK = 32;
    constexpr int NIT = K / BK;
    constexpr int ROWB = 80;
    constexpr int TILE = 128 * ROWB;
    constexpr int STAGE = 2 * TILE;

    extern __shared__ __align__(16) unsigned char sm[];

    const int tid = threadIdx.x;
    const int lane = tid & 31;
    const int wid = tid >> 5;
    const int row0 = blockIdx.x * 128;
    const int n0 = blockIdx.y * 128;
    const uint32_t sbase = smem_to_u32(sm);

    const int wm = wid >> 2;
    const int wn = wid & 3;
    const int m0w = wm * 64;
    const int n0w = wn * 32;

    float acc[4][4][4];
#pragma unroll
    for (int mt = 0; mt < 4; mt++)
#pragma unroll
        for (int nt = 0; nt < 4; nt++)
#pragma unroll
            for (int j = 0; j < 4; j++) acc[mt][nt][j] = 0.f;

    auto load_stage = [&](int kc, int st) {
#pragma unroll
        for (int t = 0; t < 2; t++) {
            int i = tid + t * 256;
            int r = i >> 2, q = i & 3;
            size_t gcol = (size_t)kc * BK + q * 8;
            uint32_t sa = sbase + st * STAGE + (uint32_t)(r * ROWB + q * 16);
            int grow = row0 + r;
            uint32_t pb = (grow < nrows) ? 16u : 0u;
            int gr = (grow < nrows) ? grow : 0;
            cp_async16(sa,        A + (size_t)gr * K + gcol, pb);
            int brow = n0 + r;
            cp_async16(sa + TILE, W + (size_t)brow * K + gcol, 16u);
        }
    };

    load_stage(0, 0);
    CP_COMMIT();

    for (int kc = 0; kc < NIT; kc++) {
        if (kc + 1 < NIT) {
            load_stage(kc + 1, (kc + 1) & 1);
            CP_COMMIT();
            CP_WAIT1();
        } else {
            CP_WAIT0();
        }
        __syncthreads();

        uint32_t stoff = (uint32_t)((kc & 1) * STAGE);
#pragma unroll
        for (int ks = 0; ks < 2; ks++) {
            uint32_t ah[4][4], bh[4][2];
#pragma unroll
            for (int mt = 0; mt < 4; mt++) {
                uint32_t addr = sbase + stoff +
                    (uint32_t)((m0w + mt * 16 + (lane & 15)) * ROWB + (ks * 2 + (lane >> 4)) * 16);
                LDSM_X4(ah[mt], addr);
            }
#pragma unroll
            for (int nt = 0; nt < 4; nt++) {
                uint32_t addr = sbase + stoff + TILE +
                    (uint32_t)((n0w + nt * 8 + (lane & 7)) * ROWB + (ks * 2 + ((lane >> 3) & 1)) * 16);
                LDSM_X2(bh[nt], addr);
            }
#pragma unroll
            for (int mt = 0; mt < 4; mt++)
#pragma unroll
                for (int nt = 0; nt < 4; nt++)
                    mma_f16(acc[mt][nt], ah[mt], bh[nt]);
        }
        __syncthreads();
    }

#pragma unroll
    for (int mt = 0; mt < 4; mt++) {
        int rlo = row0 + m0w + mt * 16 + (lane >> 2);
        int rhi = rlo + 8;
#pragma unroll
        for (int nt = 0; nt < 4; nt++) {
            int gn = n0 + n0w + nt * 8 + (lane & 3) * 2;
            bool isg = gn < NHALF;
            int col = isg ? gn : gn - NHALF;
            if (isg) {
                if (rlo < nrows)
                    *reinterpret_cast<__half2*>(out_gcn + (size_t)rlo * NHALF + col) =
                        __floats2half2_rn(acc[mt][nt][0], acc[mt][nt][1]);
                if (rhi < nrows)
                    *reinterpret_cast<__half2*>(out_gcn + (size_t)rhi * NHALF + col) =
                        __floats2half2_rn(acc[mt][nt][2], acc[mt][nt][3]);
            } else {
                float bx = __ldg(&bias[col]), by = __ldg(&bias[col + 1]);
                if (rlo < nrows)
                    *reinterpret_cast<float2*>(out_self + (size_t)rlo * NHALF + col) =
                        make_float2(acc[mt][nt][0] + bx, acc[mt][nt][1] + by);
                if (rhi < nrows)
                    *reinterpret_cast<float2*>(out_self + (size_t)rhi * NHALF + col) =
                        make_float2(acc[mt][nt][2] + bx, acc[mt][nt][3] + by);
            }
        }
    }
}

// ================= CSR aggregation + BN fused (half-warp per edge, LDG.128) ============
__global__ void __launch_bounds__(256) agg_bn12_kernel(
    const __half* __restrict__ hw, const float* __restrict__ selfacc,
    const float* __restrict__ gamma, const float* __restrict__ beta,
    const float* __restrict__ mean, const float* __restrict__ var,
    __half* __restrict__ hout)
{
    int v = (blockIdx.x * blockDim.x + threadIdx.x) >> 5;
    if (v >= NN) return;
    int lane = threadIdx.x & 31;
    int half = lane >> 4;      // 0: even edge, 1: odd edge
    int l16 = lane & 15;       // 8-channel group within row
    int beg = g_rowptr[v], end = g_rowptr[v + 1];

    float acc[8];
#pragma unroll
    for (int j = 0; j < 8; j++) acc[j] = 0.f;

    // two pairs in flight (4 edges per iteration), guards via w=0
    for (int e = beg; e < end; e += 4) {
        int ee0 = e + half;
        int ee1 = e + 2 + half;
        uint2 er0 = (ee0 < end) ? __ldg(&g_edge[ee0]) : make_uint2(0u, 0u);
        uint2 er1 = (ee1 < end) ? __ldg(&g_edge[ee1]) : make_uint2(0u, 0u);
        uint4 u0 = __ldg(reinterpret_cast<const uint4*>(hw + (size_t)er0.x * 128) + l16);
        uint4 u1 = __ldg(reinterpret_cast<const uint4*>(hw + (size_t)er1.x * 128) + l16);
        float w0 = __uint_as_float(er0.y);
        float w1 = __uint_as_float(er1.y);
        const __half2* h0 = reinterpret_cast<const __half2*>(&u0);
        const __half2* h1 = reinterpret_cast<const __half2*>(&u1);
#pragma unroll
        for (int j = 0; j < 4; j++) {
            float2 f0 = __half22float2(h0[j]);
            float2 f1 = __half22float2(h1[j]);
            acc[2 * j]     += w0 * f0.x + w1 * f1.x;
            acc[2 * j + 1] += w0 * f0.y + w1 * f1.y;
        }
    }

    // fold the two half-warps
#pragma unroll
    for (int j = 0; j < 8; j++)
        acc[j] += __shfl_xor_sync(0xffffffffu, acc[j], 16);

    if (half == 0) {
        int c = l16 * 8;
        float4 sf0 = __ldg(reinterpret_cast<const float4*>(selfacc + (size_t)v * 128 + c));
        float4 sf1 = __ldg(reinterpret_cast<const float4*>(selfacc + (size_t)v * 128 + c + 4));
        float vals[8] = { acc[0] + sf0.x, acc[1] + sf0.y, acc[2] + sf0.z, acc[3] + sf0.w,
                          acc[4] + sf1.x, acc[5] + sf1.y, acc[6] + sf1.z, acc[7] + sf1.w };
        __half2 pk[4];
#pragma unroll
        for (int p = 0; p < 4; p++) {
            float t0, t1;
            {
                int ch = c + 2 * p;
                t0 = (vals[2 * p]     - __ldg(&mean[ch]))     * rsqrtf(__ldg(&var[ch]) + EPSBN)     * __ldg(&gamma[ch])     + __ldg(&beta[ch]);
                t1 = (vals[2 * p + 1] - __ldg(&mean[ch + 1])) * rsqrtf(__ldg(&var[ch + 1]) + EPSBN) * __ldg(&gamma[ch + 1]) + __ldg(&beta[ch + 1]);
            }
            pk[p] = __floats2half2_rn(fmaxf(t0, 0.f), fmaxf(t1, 0.f));
        }
        *reinterpret_cast<uint4*>(hout + (size_t)v * 128 + c) = *reinterpret_cast<uint4*>(pk);
    }
}

__global__ void __launch_bounds__(256) agg_bn3_kernel(
    const __half* __restrict__ hw, const float* __restrict__ selfacc,
    const float* __restrict__ gamma, const float* __restrict__ beta,
    const float* __restrict__ mean, const float* __restrict__ var,
    float* __restrict__ out)
{
    int v = (blockIdx.x * blockDim.x + threadIdx.x) >> 5;
    if (v >= NN) return;
    int lane = threadIdx.x & 31;
    if (lane >= 20) return;
    int beg = g_rowptr[v], end = g_rowptr[v + 1];

    float2 acc = make_float2(0.f, 0.f);
    int e = beg;
    for (; e + 3 < end; e += 4) {
        uint2 e0 = __ldg(&g_edge[e]);
        uint2 e1 = __ldg(&g_edge[e + 1]);
        uint2 e2 = __ldg(&g_edge[e + 2]);
        uint2 e3 = __ldg(&g_edge[e + 3]);
        uint u0 = __ldg(reinterpret_cast<const uint32_t*>(hw + (size_t)e0.x * NCLS_PAD) + lane);
        uint u1 = __ldg(reinterpret_cast<const uint32_t*>(hw + (size_t)e1.x * NCLS_PAD) + lane);
        uint u2 = __ldg(reinterpret_cast<const uint32_t*>(hw + (size_t)e2.x * NCLS_PAD) + lane);
        uint u3 = __ldg(reinterpret_cast<const uint32_t*>(hw + (size_t)e3.x * NCLS_PAD) + lane);
        float2 f0 = __half22float2(*reinterpret_cast<__half2*>(&u0));
        float2 f1 = __half22float2(*reinterpret_cast<__half2*>(&u1));
        float2 f2 = __half22float2(*reinterpret_cast<__half2*>(&u2));
        float2 f3 = __half22float2(*reinterpret_cast<__half2*>(&u3));
        float w0 = __uint_as_float(e0.y), w1 = __uint_as_float(e1.y);
        float w2 = __uint_as_float(e2.y), w3 = __uint_as_float(e3.y);
        acc.x += w0 * f0.x + w1 * f1.x + w2 * f2.x + w3 * f3.x;
        acc.y += w0 * f0.y + w1 * f1.y + w2 * f2.y + w3 * f3.y;
    }
    for (; e < end; e++) {
        uint2 e0 = __ldg(&g_edge[e]);
        float w0 = __uint_as_float(e0.y);
        uint u0 = __ldg(reinterpret_cast<const uint32_t*>(hw + (size_t)e0.x * NCLS_PAD) + lane);
        float2 f0 = __half22float2(*reinterpret_cast<__half2*>(&u0));
        acc.x += w0 * f0.x;
        acc.y += w0 * f0.y;
    }

    float2 sf = __ldg(reinterpret_cast<const float2*>(selfacc + (size_t)v * NCLS_PAD) + lane);
    int c = lane * 2;
    float2 o;
    o.x = (acc.x + sf.x - __ldg(&mean[c]))     * rsqrtf(__ldg(&var[c]) + EPSBN)     * __ldg(&gamma[c])     + __ldg(&beta[c]);
    o.y = (acc.y + sf.y - __ldg(&mean[c + 1])) * rsqrtf(__ldg(&var[c + 1]) + EPSBN) * __ldg(&gamma[c + 1]) + __ldg(&beta[c + 1]);
    *reinterpret_cast<float2*>(out + (size_t)v * NCLS + c) = o;
}

// ================= launch =================
extern "C" void kernel_launch(void* const* d_in, const int* in_sizes, int n_in,
                              void* d_out, int out_size) {
    const float* x   = (const float*)d_in[0];
    const int*   ei  = (const int*)d_in[1];
    const float* ew  = (const float*)d_in[2];
    const int* src = ei;
    const int* dst = ei + EE;

    const float* wg1 = (const float*)d_in[3];
    const float* ws1 = (const float*)d_in[4];
    const float* b1  = (const float*)d_in[5];
    const float* gm1 = (const float*)d_in[6];
    const float* bt1 = (const float*)d_in[7];
    const float* mn1 = (const float*)d_in[8];
    const float* vr1 = (const float*)d_in[9];

    const float* wg2 = (const float*)d_in[10];
    const float* ws2 = (const float*)d_in[11];
    const float* b2  = (const float*)d_in[12];
    const float* gm2 = (const float*)d_in[13];
    const float* bt2 = (const float*)d_in[14];
    const float* mn2 = (const float*)d_in[15];
    const float* vr2 = (const float*)d_in[16];

    const float* wg3 = (const float*)d_in[17];
    const float* ws3 = (const float*)d_in[18];
    const float* b3  = (const float*)d_in[19];
    const float* gm3 = (const float*)d_in[20];
    const float* bt3 = (const float*)d_in[21];
    const float* mn3 = (const float*)d_in[22];
    const float* vr3 = (const float*)d_in[23];

    float* out = (float*)d_out;

    float *p_acc, *p_b3p;
    __half *p_hwh, *p_xh, *p_hh, *p_w1h, *p_w2h, *p_w3h;
    cudaGetSymbolAddress((void**)&p_hwh, g_hwh);
    cudaGetSymbolAddress((void**)&p_acc, g_acc);
    cudaGetSymbolAddress((void**)&p_b3p, g_b3p);
    cudaGetSymbolAddress((void**)&p_xh,  g_xh);
    cudaGetSymbolAddress((void**)&p_hh,  g_hh);
    cudaGetSymbolAddress((void**)&p_w1h, g_w1h);
    cudaGetSymbolAddress((void**)&p_w2h, g_w2h);
    cudaGetSymbolAddress((void**)&p_w3h, g_w3h);

    const int GSMEM = 2 * 2 * 128 * 80;  // 40960 bytes

    static cudaStream_t s2 = nullptr;
    static cudaEvent_t ev_fork = nullptr, ev_join = nullptr;
    if (s2 == nullptr) {
        cudaStreamCreateWithFlags(&s2, cudaStreamNonBlocking);
        cudaEventCreateWithFlags(&ev_fork, cudaEventDisableTiming);
        cudaEventCreateWithFlags(&ev_join, cudaEventDisableTiming);
    }

    const int TPB = 256;
    const int GRID_M = (NN + 127) / 128;           // 391
    const int GRID_W = (NN * 32 + TPB - 1) / TPB;

    // ---- fork: CSR build chain on side stream ----
    cudaEventRecord(ev_fork, 0);
    cudaStreamWaitEvent(s2, ev_fork, 0);
    zero_dc_kernel<<<(NN + TPB - 1) / TPB, TPB, 0, s2>>>();
    count_deg_kernel<<<(EE + TPB - 1) / TPB, TPB, 0, s2>>>(dst, ew, EE);
    blocksum_dinv_kernel<<<NBLK, SCAN_B, 0, s2>>>();
    scatter_rowptr_kernel<<<NBLK, SCAN_B, 0, s2>>>();
    fill_kernel<<<(EE + TPB - 1) / TPB, TPB, 0, s2>>>(src, dst, ew, EE);
    cudaEventRecord(ev_join, s2);

    // ---- main stream: prep + convert + layer-1 GEMM ----
    prep_w_kernel<<<(2 * 128 * 256 + TPB - 1) / TPB, TPB>>>(wg1, ws1, 256, 128, 128, p_w1h);
    prep_w_kernel<<<(2 * 128 * 128 + TPB - 1) / TPB, TPB>>>(wg2, ws2, 128, 128, 128, p_w2h);
    prep_w_kernel<<<(2 * 64 * 128 + TPB - 1) / TPB, TPB>>>(wg3, ws3, 128, 40, 64, p_w3h);
    prep_b3_kernel<<<1, 64>>>(b3);
    split_kernel<<<(NN * F_IN + TPB - 1) / TPB, TPB>>>(x, p_xh, NN * F_IN);
    gcn_gemm_mma<256, 128><<<dim3(GRID_M, 2), 256, GSMEM>>>(p_xh, p_w1h, b1, p_hwh, p_acc, NN);

    // ---- join ----
    cudaStreamWaitEvent(0, ev_join, 0);
    agg_bn12_kernel<<<GRID_W, TPB>>>(p_hwh, p_acc, gm1, bt1, mn1, vr1, p_hh);

    // ---- layer 2 ----
    gcn_gemm_mma<128, 128><<<dim3(GRID_M, 2), 256, GSMEM>>>(p_hh, p_w2h, b2, p_hwh, p_acc, NN);
    agg_bn12_kernel<<<GRID_W, TPB>>>(p_hwh, p_acc, gm2, bt2, mn2, vr2, p_hh);

    // ---- layer 3 ----
    gcn_gemm_mma<128, 64><<<dim3(GRID_M, 1), 256, GSMEM>>>(p_hh, p_w3h, p_b3p, p_hwh, p_acc, NN);
    agg_bn3_kernel<<<GRID_W, TPB>>>(p_hwh, p_acc, gm3, bt3, mn3, vr3, out);
}

// round 13
// speedup vs baseline: 1.0956x; 1.0956x over previous
#include <cuda_runtime.h>
#include <cuda_bf16.h>
#include <cuda_fp16.h>
#include <cstdint>

// Problem constants
#define NN 50000
#define EE 1000000
#define F_IN 256
#define UNITS 128
#define NCLS 40
#define NCLS_PAD 64
#define EPSBN 1e-3f

#define SCAN_B 256
#define NBLK ((NN + SCAN_B - 1) / SCAN_B)   // 196

// ================= mma.sync / cp.async helpers =================
__device__ __forceinline__ uint32_t smem_to_u32(const void* p) {
    uint32_t a;
    asm("{ .reg .u64 t; cvta.to.shared.u64 t, %1; cvt.u32.u64 %0, t; }" : "=r"(a) : "l"(p));
    return a;
}
#define LDSM_X4(r, addr) \
    asm volatile("ldmatrix.sync.aligned.m8n8.x4.shared.b16 {%0,%1,%2,%3}, [%4];" \
        : "=r"((r)[0]), "=r"((r)[1]), "=r"((r)[2]), "=r"((r)[3]) : "r"(addr))
#define LDSM_X2(r, addr) \
    asm volatile("ldmatrix.sync.aligned.m8n8.x2.shared.b16 {%0,%1}, [%2];" \
        : "=r"((r)[0]), "=r"((r)[1]) : "r"(addr))

__device__ __forceinline__ void mma_f16(float* c, const uint32_t* a, const uint32_t* b) {
    asm volatile("mma.sync.aligned.m16n8k16.row.col.f32.f16.f16.f32 "
        "{%0,%1,%2,%3}, {%4,%5,%6,%7}, {%8,%9}, {%0,%1,%2,%3};"
        : "+f"(c[0]), "+f"(c[1]), "+f"(c[2]), "+f"(c[3])
        : "r"(a[0]), "r"(a[1]), "r"(a[2]), "r"(a[3]), "r"(b[0]), "r"(b[1]));
}
__device__ __forceinline__ void cp_async16(uint32_t sa, const void* g, uint32_t pbytes) {
    asm volatile("cp.async.cg.shared.global [%0], [%1], 16, %2;"
                 :: "r"(sa), "l"(g), "r"(pbytes) : "memory");
}
#define CP_COMMIT() asm volatile("cp.async.commit_group;" ::: "memory")
#define CP_WAIT0()  asm volatile("cp.async.wait_group 0;" ::: "memory")
#define CP_WAIT1()  asm volatile("cp.async.wait_group 1;" ::: "memory")

// ================= scratch (static device globals) =================
__device__ __align__(16) float g_deg[NN];
__device__ __align__(16) int   g_cnt[NN];
__device__ __align__(16) int   g_rowptr[NN + 1];
__device__ __align__(16) int   g_bsum[NBLK];
__device__ __align__(16) uint2 g_edge[EE];                 // packed (src, norm_w)
__device__ __align__(16) __half g_hwh[(size_t)NN * 128];   // fp16 gcn-path GEMM output
__device__ __align__(16) float g_acc[(size_t)NN * 128];    // fp32 self path
__device__ __align__(16) __half g_xh[(size_t)NN * F_IN];   // fp16 input features
__device__ __align__(16) __half g_hh[(size_t)NN * 128];    // fp16 layer activations
__device__ __align__(16) __half g_w1h[256 * 256];
__device__ __align__(16) __half g_w2h[256 * 128];
__device__ __align__(16) __half g_w3h[128 * 128];
__device__ __align__(16) float g_b3p[NCLS_PAD];

// ================= CSR build =================
__global__ void zero_dc_kernel() {
    int i = blockIdx.x * blockDim.x + threadIdx.x;
    if (i < NN) { g_deg[i] = 0.f; g_cnt[i] = 0; }
}
__global__ void count_deg_kernel(const int* __restrict__ dst, const float* __restrict__ w, int e) {
    int i = blockIdx.x * blockDim.x + threadIdx.x;
    if (i < e) {
        int d = dst[i];
        atomicAdd(&g_cnt[d], 1);
        atomicAdd(&g_deg[d], w[i]);
    }
}
__global__ void __launch_bounds__(SCAN_B) blocksum_dinv_kernel() {
    __shared__ int sh[SCAN_B];
    int i = blockIdx.x * SCAN_B + threadIdx.x;
    int v = 0;
    if (i < NN) {
        v = g_cnt[i];
        float d = g_deg[i];
        g_deg[i] = (d > 0.f) ? rsqrtf(d) : 0.f;
    }
    sh[threadIdx.x] = v;
    __syncthreads();
    for (int off = SCAN_B / 2; off > 0; off >>= 1) {
        if (threadIdx.x < off) sh[threadIdx.x] += sh[threadIdx.x + off];
        __syncthreads();
    }
    if (threadIdx.x == 0) g_bsum[blockIdx.x] = sh[0];
}
__global__ void __launch_bounds__(SCAN_B) scatter_rowptr_kernel() {
    __shared__ int sh[SCAN_B];
    __shared__ int red[SCAN_B];
    int i = blockIdx.x * SCAN_B + threadIdx.x;
    int t = threadIdx.x;
    int bv = (t < NBLK) ? g_bsum[t] : 0;
    red[t] = (t < blockIdx.x) ? bv : 0;
    sh[t] = bv;
    __syncthreads();
    for (int off = SCAN_B / 2; off > 0; off >>= 1) {
        if (t < off) { red[t] += red[t + off]; sh[t] += sh[t + off]; }
        __syncthreads();
    }
    int boff = red[0];
    int total = sh[0];
    __syncthreads();
    int v = (i < NN) ? g_cnt[i] : 0;
    sh[t] = v;
    __syncthreads();
    for (int off = 1; off < SCAN_B; off <<= 1) {
        int u = (t >= off) ? sh[t - off] : 0;
        __syncthreads();
        sh[t] += u;
        __syncthreads();
    }
    if (i < NN) {
        g_rowptr[i] = boff + sh[t] - v;
        g_cnt[i] = 0;
    }
    if (blockIdx.x == NBLK - 1 && t == 0) g_rowptr[NN] = total;
}
__global__ void fill_kernel(const int* __restrict__ src, const int* __restrict__ dst,
                            const float* __restrict__ w, int e) {
    int i = blockIdx.x * blockDim.x + threadIdx.x;
    if (i >= e) return;
    int s = src[i], d = dst[i];
    int pos = g_rowptr[d] + atomicAdd(&g_cnt[d], 1);
    float nw = g_deg[s] * w[i] * g_deg[d];
    g_edge[pos] = make_uint2((uint32_t)s, __float_as_uint(nw));
}

// ================= prep kernels =================
__global__ void prep_w_kernel(const float* __restrict__ Wg, const float* __restrict__ Ws,
                              int K, int NV, int NHALF, __half* __restrict__ wout) {
    int idx = blockIdx.x * blockDim.x + threadIdx.x;
    int total = 2 * NHALF * K;
    if (idx >= total) return;
    int n = idx / K, k = idx - n * K;
    float v = 0.f;
    if (n < NHALF) { if (n < NV) v = Wg[k * NV + n]; }
    else { int c = n - NHALF; if (c < NV) v = Ws[k * NV + c]; }
    wout[idx] = __float2half_rn(v);
}
__global__ void prep_b3_kernel(const float* __restrict__ b) {
    int i = threadIdx.x;
    if (i < NCLS_PAD) g_b3p[i] = (i < NCLS) ? b[i] : 0.f;
}
__global__ void split_kernel(const float* __restrict__ in, __half* __restrict__ o, int n) {
    int i = blockIdx.x * blockDim.x + threadIdx.x;
    if (i < n) o[i] = __float2half_rn(in[i]);
}

// ================= cp.async double-buffered fp16 GEMM; gcn out fp16 =================
template<int K, int NHALF>
__global__ void __launch_bounds__(256) gcn_gemm_mma(
    const __half* __restrict__ A, const __half* __restrict__ W,
    const float* __restrict__ bias,
    __half* __restrict__ out_gcn, float* __restrict__ out_self, int nrows)
{
    constexpr int BK = 32;
    constexpr int NIT = K / BK;
    constexpr int ROWB = 80;
    constexpr int TILE = 128 * ROWB;
    constexpr int STAGE = 2 * TILE;

    extern __shared__ __align__(16) unsigned char sm[];

    const int tid = threadIdx.x;
    const int lane = tid & 31;
    const int wid = tid >> 5;
    const int row0 = blockIdx.x * 128;
    const int n0 = blockIdx.y * 128;
    const uint32_t sbase = smem_to_u32(sm);

    const int wm = wid >> 2;
    const int wn = wid & 3;
    const int m0w = wm * 64;
    const int n0w = wn * 32;

    float acc[4][4][4];
#pragma unroll
    for (int mt = 0; mt < 4; mt++)
#pragma unroll
        for (int nt = 0; nt < 4; nt++)
#pragma unroll
            for (int j = 0; j < 4; j++) acc[mt][nt][j] = 0.f;

    auto load_stage = [&](int kc, int st) {
#pragma unroll
        for (int t = 0; t < 2; t++) {
            int i = tid + t * 256;
            int r = i >> 2, q = i & 3;
            size_t gcol = (size_t)kc * BK + q * 8;
            uint32_t sa = sbase + st * STAGE + (uint32_t)(r * ROWB + q * 16);
            int grow = row0 + r;
            uint32_t pb = (grow < nrows) ? 16u : 0u;
            int gr = (grow < nrows) ? grow : 0;
            cp_async16(sa,        A + (size_t)gr * K + gcol, pb);
            int brow = n0 + r;
            cp_async16(sa + TILE, W + (size_t)brow * K + gcol, 16u);
        }
    };

    load_stage(0, 0);
    CP_COMMIT();

    for (int kc = 0; kc < NIT; kc++) {
        if (kc + 1 < NIT) {
            load_stage(kc + 1, (kc + 1) & 1);
            CP_COMMIT();
            CP_WAIT1();
        } else {
            CP_WAIT0();
        }
        __syncthreads();

        uint32_t stoff = (uint32_t)((kc & 1) * STAGE);
#pragma unroll
        for (int ks = 0; ks < 2; ks++) {
            uint32_t ah[4][4], bh[4][2];
#pragma unroll
            for (int mt = 0; mt < 4; mt++) {
                uint32_t addr = sbase + stoff +
                    (uint32_t)((m0w + mt * 16 + (lane & 15)) * ROWB + (ks * 2 + (lane >> 4)) * 16);
                LDSM_X4(ah[mt], addr);
            }
#pragma unroll
            for (int nt = 0; nt < 4; nt++) {
                uint32_t addr = sbase + stoff + TILE +
                    (uint32_t)((n0w + nt * 8 + (lane & 7)) * ROWB + (ks * 2 + ((lane >> 3) & 1)) * 16);
                LDSM_X2(bh[nt], addr);
            }
#pragma unroll
            for (int mt = 0; mt < 4; mt++)
#pragma unroll
                for (int nt = 0; nt < 4; nt++)
                    mma_f16(acc[mt][nt], ah[mt], bh[nt]);
        }
        __syncthreads();
    }

#pragma unroll
    for (int mt = 0; mt < 4; mt++) {
        int rlo = row0 + m0w + mt * 16 + (lane >> 2);
        int rhi = rlo + 8;
#pragma unroll
        for (int nt = 0; nt < 4; nt++) {
            int gn = n0 + n0w + nt * 8 + (lane & 3) * 2;
            bool isg = gn < NHALF;
            int col = isg ? gn : gn - NHALF;
            if (isg) {
                if (rlo < nrows)
                    *reinterpret_cast<__half2*>(out_gcn + (size_t)rlo * NHALF + col) =
                        __floats2half2_rn(acc[mt][nt][0], acc[mt][nt][1]);
                if (rhi < nrows)
                    *reinterpret_cast<__half2*>(out_gcn + (size_t)rhi * NHALF + col) =
                        __floats2half2_rn(acc[mt][nt][2], acc[mt][nt][3]);
            } else {
                float bx = __ldg(&bias[col]), by = __ldg(&bias[col + 1]);
                if (rlo < nrows)
                    *reinterpret_cast<float2*>(out_self + (size_t)rlo * NHALF + col) =
                        make_float2(acc[mt][nt][0] + bx, acc[mt][nt][1] + by);
                if (rhi < nrows)
                    *reinterpret_cast<float2*>(out_self + (size_t)rhi * NHALF + col) =
                        make_float2(acc[mt][nt][2] + bx, acc[mt][nt][3] + by);
            }
        }
    }
}

// ================= CSR aggregation + BN fused (packed edges, 8x unrolled) =================
__global__ void __launch_bounds__(256) agg_bn12_kernel(
    const __half* __restrict__ hw, const float* __restrict__ selfacc,
    const float* __restrict__ gamma, const float* __restrict__ beta,
    const float* __restrict__ mean, const float* __restrict__ var,
    __half* __restrict__ hout)
{
    int v = (blockIdx.x * blockDim.x + threadIdx.x) >> 5;
    if (v >= NN) return;
    int lane = threadIdx.x & 31;
    int beg = g_rowptr[v], end = g_rowptr[v + 1];

    float4 acc = make_float4(0.f, 0.f, 0.f, 0.f);
    int e = beg;
    for (; e + 7 < end; e += 8) {
        uint2 er[8];
        uint2 u[8];
#pragma unroll
        for (int q = 0; q < 8; q++) er[q] = __ldg(&g_edge[e + q]);
#pragma unroll
        for (int q = 0; q < 8; q++)
            u[q] = __ldg(reinterpret_cast<const uint2*>(hw + (size_t)er[q].x * 128) + lane);
#pragma unroll
        for (int q = 0; q < 8; q++) {
            float w = __uint_as_float(er[q].y);
            float2 a = __half22float2(*reinterpret_cast<__half2*>(&u[q].x));
            float2 b = __half22float2(*reinterpret_cast<__half2*>(&u[q].y));
            acc.x += w * a.x;
            acc.y += w * a.y;
            acc.z += w * b.x;
            acc.w += w * b.y;
        }
    }
    for (; e + 3 < end; e += 4) {
        uint2 er[4];
        uint2 u[4];
#pragma unroll
        for (int q = 0; q < 4; q++) er[q] = __ldg(&g_edge[e + q]);
#pragma unroll
        for (int q = 0; q < 4; q++)
            u[q] = __ldg(reinterpret_cast<const uint2*>(hw + (size_t)er[q].x * 128) + lane);
#pragma unroll
        for (int q = 0; q < 4; q++) {
            float w = __uint_as_float(er[q].y);
            float2 a = __half22float2(*reinterpret_cast<__half2*>(&u[q].x));
            float2 b = __half22float2(*reinterpret_cast<__half2*>(&u[q].y));
            acc.x += w * a.x;
            acc.y += w * a.y;
            acc.z += w * b.x;
            acc.w += w * b.y;
        }
    }
    for (; e < end; e++) {
        uint2 e0 = __ldg(&g_edge[e]);
        float w0 = __uint_as_float(e0.y);
        uint2 u0 = __ldg(reinterpret_cast<const uint2*>(hw + (size_t)e0.x * 128) + lane);
        float2 a0 = __half22float2(*reinterpret_cast<__half2*>(&u0.x));
        float2 b0 = __half22float2(*reinterpret_cast<__half2*>(&u0.y));
        acc.x += w0 * a0.x; acc.y += w0 * a0.y; acc.z += w0 * b0.x; acc.w += w0 * b0.y;
    }

    float4 sf = __ldg(reinterpret_cast<const float4*>(selfacc + (size_t)v * 128) + lane);
    int c = lane * 4;
    float vals[4] = { acc.x + sf.x, acc.y + sf.y, acc.z + sf.z, acc.w + sf.w };
#pragma unroll
    for (int j = 0; j < 4; j++) {
        int ch = c + j;
        float t = vals[j];
        t = (t - __ldg(&mean[ch])) * rsqrtf(__ldg(&var[ch]) + EPSBN) * __ldg(&gamma[ch]) + __ldg(&beta[ch]);
        vals[j] = fmaxf(t, 0.f);
    }
    __half2 p0 = __floats2half2_rn(vals[0], vals[1]);
    __half2 p1 = __floats2half2_rn(vals[2], vals[3]);
    uint2 pk;
    pk.x = *reinterpret_cast<uint32_t*>(&p0);
    pk.y = *reinterpret_cast<uint32_t*>(&p1);
    *reinterpret_cast<uint2*>(hout + (size_t)v * 128 + c) = pk;
}

__global__ void __launch_bounds__(256) agg_bn3_kernel(
    const __half* __restrict__ hw, const float* __restrict__ selfacc,
    const float* __restrict__ gamma, const float* __restrict__ beta,
    const float* __restrict__ mean, const float* __restrict__ var,
    float* __restrict__ out)
{
    int v = (blockIdx.x * blockDim.x + threadIdx.x) >> 5;
    if (v >= NN) return;
    int lane = threadIdx.x & 31;
    if (lane >= 20) return;
    int beg = g_rowptr[v], end = g_rowptr[v + 1];

    float2 acc = make_float2(0.f, 0.f);
    int e = beg;
    for (; e + 3 < end; e += 4) {
        uint2 e0 = __ldg(&g_edge[e]);
        uint2 e1 = __ldg(&g_edge[e + 1]);
        uint2 e2 = __ldg(&g_edge[e + 2]);
        uint2 e3 = __ldg(&g_edge[e + 3]);
        uint u0 = __ldg(reinterpret_cast<const uint32_t*>(hw + (size_t)e0.x * NCLS_PAD) + lane);
        uint u1 = __ldg(reinterpret_cast<const uint32_t*>(hw + (size_t)e1.x * NCLS_PAD) + lane);
        uint u2 = __ldg(reinterpret_cast<const uint32_t*>(hw + (size_t)e2.x * NCLS_PAD) + lane);
        uint u3 = __ldg(reinterpret_cast<const uint32_t*>(hw + (size_t)e3.x * NCLS_PAD) + lane);
        float2 f0 = __half22float2(*reinterpret_cast<__half2*>(&u0));
        float2 f1 = __half22float2(*reinterpret_cast<__half2*>(&u1));
        float2 f2 = __half22float2(*reinterpret_cast<__half2*>(&u2));
        float2 f3 = __half22float2(*reinterpret_cast<__half2*>(&u3));
        float w0 = __uint_as_float(e0.y), w1 = __uint_as_float(e1.y);
        float w2 = __uint_as_float(e2.y), w3 = __uint_as_float(e3.y);
        acc.x += w0 * f0.x + w1 * f1.x + w2 * f2.x + w3 * f3.x;
        acc.y += w0 * f0.y + w1 * f1.y + w2 * f2.y + w3 * f3.y;
    }
    for (; e < end; e++) {
        uint2 e0 = __ldg(&g_edge[e]);
        float w0 = __uint_as_float(e0.y);
        uint u0 = __ldg(reinterpret_cast<const uint32_t*>(hw + (size_t)e0.x * NCLS_PAD) + lane);
        float2 f0 = __half22float2(*reinterpret_cast<__half2*>(&u0));
        acc.x += w0 * f0.x;
        acc.y += w0 * f0.y;
    }

    float2 sf = __ldg(reinterpret_cast<const float2*>(selfacc + (size_t)v * NCLS_PAD) + lane);
    int c = lane * 2;
    float2 o;
    o.x = (acc.x + sf.x - __ldg(&mean[c]))     * rsqrtf(__ldg(&var[c]) + EPSBN)     * __ldg(&gamma[c])     + __ldg(&beta[c]);
    o.y = (acc.y + sf.y - __ldg(&mean[c + 1])) * rsqrtf(__ldg(&var[c + 1]) + EPSBN) * __ldg(&gamma[c + 1]) + __ldg(&beta[c + 1]);
    *reinterpret_cast<float2*>(out + (size_t)v * NCLS + c) = o;
}

// ================= launch =================
extern "C" void kernel_launch(void* const* d_in, const int* in_sizes, int n_in,
                              void* d_out, int out_size) {
    const float* x   = (const float*)d_in[0];
    const int*   ei  = (const int*)d_in[1];
    const float* ew  = (const float*)d_in[2];
    const int* src = ei;
    const int* dst = ei + EE;

    const float* wg1 = (const float*)d_in[3];
    const float* ws1 = (const float*)d_in[4];
    const float* b1  = (const float*)d_in[5];
    const float* gm1 = (const float*)d_in[6];
    const float* bt1 = (const float*)d_in[7];
    const float* mn1 = (const float*)d_in[8];
    const float* vr1 = (const float*)d_in[9];

    const float* wg2 = (const float*)d_in[10];
    const float* ws2 = (const float*)d_in[11];
    const float* b2  = (const float*)d_in[12];
    const float* gm2 = (const float*)d_in[13];
    const float* bt2 = (const float*)d_in[14];
    const float* mn2 = (const float*)d_in[15];
    const float* vr2 = (const float*)d_in[16];

    const float* wg3 = (const float*)d_in[17];
    const float* ws3 = (const float*)d_in[18];
    const float* b3  = (const float*)d_in[19];
    const float* gm3 = (const float*)d_in[20];
    const float* bt3 = (const float*)d_in[21];
    const float* mn3 = (const float*)d_in[22];
    const float* vr3 = (const float*)d_in[23];

    float* out = (float*)d_out;

    float *p_acc, *p_b3p;
    __half *p_hwh, *p_xh, *p_hh, *p_w1h, *p_w2h, *p_w3h;
    cudaGetSymbolAddress((void**)&p_hwh, g_hwh);
    cudaGetSymbolAddress((void**)&p_acc, g_acc);
    cudaGetSymbolAddress((void**)&p_b3p, g_b3p);
    cudaGetSymbolAddress((void**)&p_xh,  g_xh);
    cudaGetSymbolAddress((void**)&p_hh,  g_hh);
    cudaGetSymbolAddress((void**)&p_w1h, g_w1h);
    cudaGetSymbolAddress((void**)&p_w2h, g_w2h);
    cudaGetSymbolAddress((void**)&p_w3h, g_w3h);

    const int GSMEM = 2 * 2 * 128 * 80;  // 40960 bytes

    static cudaStream_t s2 = nullptr;
    static cudaEvent_t ev_fork = nullptr, ev_join = nullptr;
    if (s2 == nullptr) {
        cudaStreamCreateWithFlags(&s2, cudaStreamNonBlocking);
        cudaEventCreateWithFlags(&ev_fork, cudaEventDisableTiming);
        cudaEventCreateWithFlags(&ev_join, cudaEventDisableTiming);
    }

    const int TPB = 256;
    const int GRID_M = (NN + 127) / 128;           // 391
    const int GRID_W = (NN * 32 + TPB - 1) / TPB;

    // ---- fork: CSR build chain on side stream ----
    cudaEventRecord(ev_fork, 0);
    cudaStreamWaitEvent(s2, ev_fork, 0);
    zero_dc_kernel<<<(NN + TPB - 1) / TPB, TPB, 0, s2>>>();
    count_deg_kernel<<<(EE + TPB - 1) / TPB, TPB, 0, s2>>>(dst, ew, EE);
    blocksum_dinv_kernel<<<NBLK, SCAN_B, 0, s2>>>();
    scatter_rowptr_kernel<<<NBLK, SCAN_B, 0, s2>>>();
    fill_kernel<<<(EE + TPB - 1) / TPB, TPB, 0, s2>>>(src, dst, ew, EE);
    cudaEventRecord(ev_join, s2);

    // ---- main stream: prep + convert + layer-1 GEMM ----
    prep_w_kernel<<<(2 * 128 * 256 + TPB - 1) / TPB, TPB>>>(wg1, ws1, 256, 128, 128, p_w1h);
    prep_w_kernel<<<(2 * 128 * 128 + TPB - 1) / TPB, TPB>>>(wg2, ws2, 128, 128, 128, p_w2h);
    prep_w_kernel<<<(2 * 64 * 128 + TPB - 1) / TPB, TPB>>>(wg3, ws3, 128, 40, 64, p_w3h);
    prep_b3_kernel<<<1, 64>>>(b3);
    split_kernel<<<(NN * F_IN + TPB - 1) / TPB, TPB>>>(x, p_xh, NN * F_IN);
    gcn_gemm_mma<256, 128><<<dim3(GRID_M, 2), 256, GSMEM>>>(p_xh, p_w1h, b1, p_hwh, p_acc, NN);

    // ---- join ----
    cudaStreamWaitEvent(0, ev_join, 0);
    agg_bn12_kernel<<<GRID_W, TPB>>>(p_hwh, p_acc, gm1, bt1, mn1, vr1, p_hh);

    // ---- layer 2 ----
    gcn_gemm_mma<128, 128><<<dim3(GRID_M, 2), 256, GSMEM>>>(p_hh, p_w2h, b2, p_hwh, p_acc, NN);
    agg_bn12_kernel<<<GRID_W, TPB>>>(p_hwh, p_acc, gm2, bt2, mn2, vr2, p_hh);

    // ---- layer 3 ----
    gcn_gemm_mma<128, 64><<<dim3(GRID_M, 1), 256, GSMEM>>>(p_hh, p_w3h, p_b3p, p_hwh, p_acc, NN);
    agg_bn3_kernel<<<GRID_W, TPB>>>(p_hwh, p_acc, gm3, bt3, mn3, vr3, out);
}

// round 14
// speedup vs baseline: 1.1129x; 1.0158x over previous
#include <cuda_runtime.h>
#include <cuda_bf16.h>
#include <cuda_fp16.h>
#include <cstdint>

// Problem constants
#define NN 50000
#define EE 1000000
#define F_IN 256
#define UNITS 128
#define NCLS 40
#define NCLS_PAD 64
#define EPSBN 1e-3f

#define SCAN_B 256
#define NBLK ((NN + SCAN_B - 1) / SCAN_B)   // 196

// ================= mma.sync / cp.async helpers =================
__device__ __forceinline__ uint32_t smem_to_u32(const void* p) {
    uint32_t a;
    asm("{ .reg .u64 t; cvta.to.shared.u64 t, %1; cvt.u32.u64 %0, t; }" : "=r"(a) : "l"(p));
    return a;
}
#define LDSM_X4(r, addr) \
    asm volatile("ldmatrix.sync.aligned.m8n8.x4.shared.b16 {%0,%1,%2,%3}, [%4];" \
        : "=r"((r)[0]), "=r"((r)[1]), "=r"((r)[2]), "=r"((r)[3]) : "r"(addr))
#define LDSM_X2(r, addr) \
    asm volatile("ldmatrix.sync.aligned.m8n8.x2.shared.b16 {%0,%1}, [%2];" \
        : "=r"((r)[0]), "=r"((r)[1]) : "r"(addr))

__device__ __forceinline__ void mma_f16(float* c, const uint32_t* a, const uint32_t* b) {
    asm volatile("mma.sync.aligned.m16n8k16.row.col.f32.f16.f16.f32 "
        "{%0,%1,%2,%3}, {%4,%5,%6,%7}, {%8,%9}, {%0,%1,%2,%3};"
        : "+f"(c[0]), "+f"(c[1]), "+f"(c[2]), "+f"(c[3])
        : "r"(a[0]), "r"(a[1]), "r"(a[2]), "r"(a[3]), "r"(b[0]), "r"(b[1]));
}
__device__ __forceinline__ void cp_async16(uint32_t sa, const void* g, uint32_t pbytes) {
    asm volatile("cp.async.cg.shared.global [%0], [%1], 16, %2;"
                 :: "r"(sa), "l"(g), "r"(pbytes) : "memory");
}
#define CP_COMMIT() asm volatile("cp.async.commit_group;" ::: "memory")
#define CP_WAIT0()  asm volatile("cp.async.wait_group 0;" ::: "memory")
#define CP_WAIT1()  asm volatile("cp.async.wait_group 1;" ::: "memory")

// ================= scratch (static device globals) =================
__device__ __align__(16) float g_deg[NN];
__device__ __align__(16) int   g_cnt[NN];
__device__ __align__(16) int   g_rowptr[NN + 1];
__device__ __align__(16) int   g_bsum[NBLK];
__device__ __align__(16) uint2 g_edge[EE];                 // packed (src, norm_w)
__device__ __align__(16) __half g_hwh[(size_t)NN * 128];   // fp16 gcn-path GEMM output
__device__ __align__(16) float g_acc[(size_t)NN * 128];    // fp32 self path
__device__ __align__(16) __half g_xh[(size_t)NN * F_IN];   // fp16 input features
__device__ __align__(16) __half g_hh[(size_t)NN * 128];    // fp16 layer activations
__device__ __align__(16) __half g_w1h[256 * 256];
__device__ __align__(16) __half g_w2h[256 * 128];
__device__ __align__(16) __half g_w3h[128 * 128];
__device__ __align__(16) float g_b3p[NCLS_PAD];

// ================= CSR build =================
__global__ void zero_dc_kernel() {
    int i = blockIdx.x * blockDim.x + threadIdx.x;
    if (i < NN) { g_deg[i] = 0.f; g_cnt[i] = 0; }
}
__global__ void count_deg_kernel(const int* __restrict__ dst, const float* __restrict__ w, int e) {
    int i = blockIdx.x * blockDim.x + threadIdx.x;
    if (i < e) {
        int d = dst[i];
        atomicAdd(&g_cnt[d], 1);
        atomicAdd(&g_deg[d], w[i]);
    }
}
__global__ void __launch_bounds__(SCAN_B) blocksum_dinv_kernel() {
    __shared__ int sh[SCAN_B];
    int i = blockIdx.x * SCAN_B + threadIdx.x;
    int v = 0;
    if (i < NN) {
        v = g_cnt[i];
        float d = g_deg[i];
        g_deg[i] = (d > 0.f) ? rsqrtf(d) : 0.f;
    }
    sh[threadIdx.x] = v;
    __syncthreads();
    for (int off = SCAN_B / 2; off > 0; off >>= 1) {
        if (threadIdx.x < off) sh[threadIdx.x] += sh[threadIdx.x + off];
        __syncthreads();
    }
    if (threadIdx.x == 0) g_bsum[blockIdx.x] = sh[0];
}
__global__ void __launch_bounds__(SCAN_B) scatter_rowptr_kernel() {
    __shared__ int sh[SCAN_B];
    __shared__ int red[SCAN_B];
    int i = blockIdx.x * SCAN_B + threadIdx.x;
    int t = threadIdx.x;
    int bv = (t < NBLK) ? g_bsum[t] : 0;
    red[t] = (t < blockIdx.x) ? bv : 0;
    sh[t] = bv;
    __syncthreads();
    for (int off = SCAN_B / 2; off > 0; off >>= 1) {
        if (t < off) { red[t] += red[t + off]; sh[t] += sh[t + off]; }
        __syncthreads();
    }
    int boff = red[0];
    int total = sh[0];
    __syncthreads();
    int v = (i < NN) ? g_cnt[i] : 0;
    sh[t] = v;
    __syncthreads();
    for (int off = 1; off < SCAN_B; off <<= 1) {
        int u = (t >= off) ? sh[t - off] : 0;
        __syncthreads();
        sh[t] += u;
        __syncthreads();
    }
    if (i < NN) {
        g_rowptr[i] = boff + sh[t] - v;
        g_cnt[i] = 0;
    }
    if (blockIdx.x == NBLK - 1 && t == 0) g_rowptr[NN] = total;
}
__global__ void fill_kernel(const int* __restrict__ src, const int* __restrict__ dst,
                            const float* __restrict__ w, int e) {
    int i = blockIdx.x * blockDim.x + threadIdx.x;
    if (i >= e) return;
    int s = src[i], d = dst[i];
    int pos = g_rowptr[d] + atomicAdd(&g_cnt[d], 1);
    float nw = g_deg[s] * w[i] * g_deg[d];
    g_edge[pos] = make_uint2((uint32_t)s, __float_as_uint(nw));
}

// ================= prep kernels =================
__global__ void prep_w_kernel(const float* __restrict__ Wg, const float* __restrict__ Ws,
                              int K, int NV, int NHALF, __half* __restrict__ wout) {
    int idx = blockIdx.x * blockDim.x + threadIdx.x;
    int total = 2 * NHALF * K;
    if (idx >= total) return;
    int n = idx / K, k = idx - n * K;
    float v = 0.f;
    if (n < NHALF) { if (n < NV) v = Wg[k * NV + n]; }
    else { int c = n - NHALF; if (c < NV) v = Ws[k * NV + c]; }
    wout[idx] = __float2half_rn(v);
}
__global__ void prep_b3_kernel(const float* __restrict__ b) {
    int i = threadIdx.x;
    if (i < NCLS_PAD) g_b3p[i] = (i < NCLS) ? b[i] : 0.f;
}
__global__ void split_kernel(const float* __restrict__ in, __half* __restrict__ o, int n) {
    int i = blockIdx.x * blockDim.x + threadIdx.x;
    if (i < n) o[i] = __float2half_rn(in[i]);
}

// ================= cp.async double-buffered fp16 GEMM; 2 CTAs/SM =================
template<int K, int NHALF>
__global__ void __launch_bounds__(256, 2) gcn_gemm_mma(
    const __half* __restrict__ A, const __half* __restrict__ W,
    const float* __restrict__ bias,
    __half* __restrict__ out_gcn, float* __restrict__ out_self, int nrows)
{
    constexpr int BK = 32;
    constexpr int NIT = K / BK;
    constexpr int ROWB = 80;
    constexpr int TILE = 128 * ROWB;
    constexpr int STAGE = 2 * TILE;

    extern __shared__ __align__(16) unsigned char sm[];

    const int tid = threadIdx.x;
    const int lane = tid & 31;
    const int wid = tid >> 5;
    const int row0 = blockIdx.x * 128;
    const int n0 = blockIdx.y * 128;
    const uint32_t sbase = smem_to_u32(sm);

    const int wm = wid >> 2;
    const int wn = wid & 3;
    const int m0w = wm * 64;
    const int n0w = wn * 32;

    float acc[4][4][4];
#pragma unroll
    for (int mt = 0; mt < 4; mt++)
#pragma unroll
        for (int nt = 0; nt < 4; nt++)
#pragma unroll
            for (int j = 0; j < 4; j++) acc[mt][nt][j] = 0.f;

    auto load_stage = [&](int kc, int st) {
#pragma unroll
        for (int t = 0; t < 2; t++) {
            int i = tid + t * 256;
            int r = i >> 2, q = i & 3;
            size_t gcol = (size_t)kc * BK + q * 8;
            uint32_t sa = sbase + st * STAGE + (uint32_t)(r * ROWB + q * 16);
            int grow = row0 + r;
            uint32_t pb = (grow < nrows) ? 16u : 0u;
            int gr = (grow < nrows) ? grow : 0;
            cp_async16(sa,        A + (size_t)gr * K + gcol, pb);
            int brow = n0 + r;
            cp_async16(sa + TILE, W + (size_t)brow * K + gcol, 16u);
        }
    };

    load_stage(0, 0);
    CP_COMMIT();

    for (int kc = 0; kc < NIT; kc++) {
        if (kc + 1 < NIT) {
            load_stage(kc + 1, (kc + 1) & 1);
            CP_COMMIT();
            CP_WAIT1();
        } else {
            CP_WAIT0();
        }
        __syncthreads();

        uint32_t stoff = (uint32_t)((kc & 1) * STAGE);
#pragma unroll
        for (int ks = 0; ks < 2; ks++) {
            uint32_t ah[4][4], bh[4][2];
#pragma unroll
            for (int mt = 0; mt < 4; mt++) {
                uint32_t addr = sbase + stoff +
                    (uint32_t)((m0w + mt * 16 + (lane & 15)) * ROWB + (ks * 2 + (lane >> 4)) * 16);
                LDSM_X4(ah[mt], addr);
            }
#pragma unroll
            for (int nt = 0; nt < 4; nt++) {
                uint32_t addr = sbase + stoff + TILE +
                    (uint32_t)((n0w + nt * 8 + (lane & 7)) * ROWB + (ks * 2 + ((lane >> 3) & 1)) * 16);
                LDSM_X2(bh[nt], addr);
            }
#pragma unroll
            for (int mt = 0; mt < 4; mt++)
#pragma unroll
                for (int nt = 0; nt < 4; nt++)
                    mma_f16(acc[mt][nt], ah[mt], bh[nt]);
        }
        __syncthreads();
    }

#pragma unroll
    for (int mt = 0; mt < 4; mt++) {
        int rlo = row0 + m0w + mt * 16 + (lane >> 2);
        int rhi = rlo + 8;
#pragma unroll
        for (int nt = 0; nt < 4; nt++) {
            int gn = n0 + n0w + nt * 8 + (lane & 3) * 2;
            bool isg = gn < NHALF;
            int col = isg ? gn : gn - NHALF;
            if (isg) {
                if (rlo < nrows)
                    *reinterpret_cast<__half2*>(out_gcn + (size_t)rlo * NHALF + col) =
                        __floats2half2_rn(acc[mt][nt][0], acc[mt][nt][1]);
                if (rhi < nrows)
                    *reinterpret_cast<__half2*>(out_gcn + (size_t)rhi * NHALF + col) =
                        __floats2half2_rn(acc[mt][nt][2], acc[mt][nt][3]);
            } else {
                float bx = __ldg(&bias[col]), by = __ldg(&bias[col + 1]);
                if (rlo < nrows)
                    *reinterpret_cast<float2*>(out_self + (size_t)rlo * NHALF + col) =
                        make_float2(acc[mt][nt][0] + bx, acc[mt][nt][1] + by);
                if (rhi < nrows)
                    *reinterpret_cast<float2*>(out_self + (size_t)rhi * NHALF + col) =
                        make_float2(acc[mt][nt][2] + bx, acc[mt][nt][3] + by);
            }
        }
    }
}

// ================= CSR aggregation + BN fused (packed edges, 4x unrolled) =================
__global__ void __launch_bounds__(256) agg_bn12_kernel(
    const __half* __restrict__ hw, const float* __restrict__ selfacc,
    const float* __restrict__ gamma, const float* __restrict__ beta,
    const float* __restrict__ mean, const float* __restrict__ var,
    __half* __restrict__ hout)
{
    int v = (blockIdx.x * blockDim.x + threadIdx.x) >> 5;
    if (v >= NN) return;
    int lane = threadIdx.x & 31;
    int beg = g_rowptr[v], end = g_rowptr[v + 1];

    float4 acc = make_float4(0.f, 0.f, 0.f, 0.f);
    int e = beg;
    for (; e + 3 < end; e += 4) {
        uint2 er[4];
        uint2 u[4];
#pragma unroll
        for (int q = 0; q < 4; q++) er[q] = __ldg(&g_edge[e + q]);
#pragma unroll
        for (int q = 0; q < 4; q++)
            u[q] = __ldg(reinterpret_cast<const uint2*>(hw + (size_t)er[q].x * 128) + lane);
#pragma unroll
        for (int q = 0; q < 4; q++) {
            float w = __uint_as_float(er[q].y);
            float2 a = __half22float2(*reinterpret_cast<__half2*>(&u[q].x));
            float2 b = __half22float2(*reinterpret_cast<__half2*>(&u[q].y));
            acc.x += w * a.x;
            acc.y += w * a.y;
            acc.z += w * b.x;
            acc.w += w * b.y;
        }
    }
    for (; e < end; e++) {
        uint2 e0 = __ldg(&g_edge[e]);
        float w0 = __uint_as_float(e0.y);
        uint2 u0 = __ldg(reinterpret_cast<const uint2*>(hw + (size_t)e0.x * 128) + lane);
        float2 a0 = __half22float2(*reinterpret_cast<__half2*>(&u0.x));
        float2 b0 = __half22float2(*reinterpret_cast<__half2*>(&u0.y));
        acc.x += w0 * a0.x; acc.y += w0 * a0.y; acc.z += w0 * b0.x; acc.w += w0 * b0.y;
    }

    float4 sf = __ldg(reinterpret_cast<const float4*>(selfacc + (size_t)v * 128) + lane);
    int c = lane * 4;
    float vals[4] = { acc.x + sf.x, acc.y + sf.y, acc.z + sf.z, acc.w + sf.w };
#pragma unroll
    for (int j = 0; j < 4; j++) {
        int ch = c + j;
        float t = vals[j];
        t = (t - __ldg(&mean[ch])) * rsqrtf(__ldg(&var[ch]) + EPSBN) * __ldg(&gamma[ch]) + __ldg(&beta[ch]);
        vals[j] = fmaxf(t, 0.f);
    }
    __half2 p0 = __floats2half2_rn(vals[0], vals[1]);
    __half2 p1 = __floats2half2_rn(vals[2], vals[3]);
    uint2 pk;
    pk.x = *reinterpret_cast<uint32_t*>(&p0);
    pk.y = *reinterpret_cast<uint32_t*>(&p1);
    *reinterpret_cast<uint2*>(hout + (size_t)v * 128 + c) = pk;
}

__global__ void __launch_bounds__(256) agg_bn3_kernel(
    const __half* __restrict__ hw, const float* __restrict__ selfacc,
    const float* __restrict__ gamma, const float* __restrict__ beta,
    const float* __restrict__ mean, const float* __restrict__ var,
    float* __restrict__ out)
{
    int v = (blockIdx.x * blockDim.x + threadIdx.x) >> 5;
    if (v >= NN) return;
    int lane = threadIdx.x & 31;
    if (lane >= 20) return;
    int beg = g_rowptr[v], end = g_rowptr[v + 1];

    float2 acc = make_float2(0.f, 0.f);
    int e = beg;
    for (; e + 3 < end; e += 4) {
        uint2 e0 = __ldg(&g_edge[e]);
        uint2 e1 = __ldg(&g_edge[e + 1]);
        uint2 e2 = __ldg(&g_edge[e + 2]);
        uint2 e3 = __ldg(&g_edge[e + 3]);
        uint u0 = __ldg(reinterpret_cast<const uint32_t*>(hw + (size_t)e0.x * NCLS_PAD) + lane);
        uint u1 = __ldg(reinterpret_cast<const uint32_t*>(hw + (size_t)e1.x * NCLS_PAD) + lane);
        uint u2 = __ldg(reinterpret_cast<const uint32_t*>(hw + (size_t)e2.x * NCLS_PAD) + lane);
        uint u3 = __ldg(reinterpret_cast<const uint32_t*>(hw + (size_t)e3.x * NCLS_PAD) + lane);
        float2 f0 = __half22float2(*reinterpret_cast<__half2*>(&u0));
        float2 f1 = __half22float2(*reinterpret_cast<__half2*>(&u1));
        float2 f2 = __half22float2(*reinterpret_cast<__half2*>(&u2));
        float2 f3 = __half22float2(*reinterpret_cast<__half2*>(&u3));
        float w0 = __uint_as_float(e0.y), w1 = __uint_as_float(e1.y);
        float w2 = __uint_as_float(e2.y), w3 = __uint_as_float(e3.y);
        acc.x += w0 * f0.x + w1 * f1.x + w2 * f2.x + w3 * f3.x;
        acc.y += w0 * f0.y + w1 * f1.y + w2 * f2.y + w3 * f3.y;
    }
    for (; e < end; e++) {
        uint2 e0 = __ldg(&g_edge[e]);
        float w0 = __uint_as_float(e0.y);
        uint u0 = __ldg(reinterpret_cast<const uint32_t*>(hw + (size_t)e0.x * NCLS_PAD) + lane);
        float2 f0 = __half22float2(*reinterpret_cast<__half2*>(&u0));
        acc.x += w0 * f0.x;
        acc.y += w0 * f0.y;
    }

    float2 sf = __ldg(reinterpret_cast<const float2*>(selfacc + (size_t)v * NCLS_PAD) + lane);
    int c = lane * 2;
    float2 o;
    o.x = (acc.x + sf.x - __ldg(&mean[c]))     * rsqrtf(__ldg(&var[c]) + EPSBN)     * __ldg(&gamma[c])     + __ldg(&beta[c]);
    o.y = (acc.y + sf.y - __ldg(&mean[c + 1])) * rsqrtf(__ldg(&var[c + 1]) + EPSBN) * __ldg(&gamma[c + 1]) + __ldg(&beta[c + 1]);
    *reinterpret_cast<float2*>(out + (size_t)v * NCLS + c) = o;
}

// ================= launch =================
extern "C" void kernel_launch(void* const* d_in, const int* in_sizes, int n_in,
                              void* d_out, int out_size) {
    const float* x   = (const float*)d_in[0];
    const int*   ei  = (const int*)d_in[1];
    const float* ew  = (const float*)d_in[2];
    const int* src = ei;
    const int* dst = ei + EE;

    const float* wg1 = (const float*)d_in[3];
    const float* ws1 = (const float*)d_in[4];
    const float* b1  = (const float*)d_in[5];
    const float* gm1 = (const float*)d_in[6];
    const float* bt1 = (const float*)d_in[7];
    const float* mn1 = (const float*)d_in[8];
    const float* vr1 = (const float*)d_in[9];

    const float* wg2 = (const float*)d_in[10];
    const float* ws2 = (const float*)d_in[11];
    const float* b2  = (const float*)d_in[12];
    const float* gm2 = (const float*)d_in[13];
    const float* bt2 = (const float*)d_in[14];
    const float* mn2 = (const float*)d_in[15];
    const float* vr2 = (const float*)d_in[16];

    const float* wg3 = (const float*)d_in[17];
    const float* ws3 = (const float*)d_in[18];
    const float* b3  = (const float*)d_in[19];
    const float* gm3 = (const float*)d_in[20];
    const float* bt3 = (const float*)d_in[21];
    const float* mn3 = (const float*)d_in[22];
    const float* vr3 = (const float*)d_in[23];

    float* out = (float*)d_out;

    float *p_acc, *p_b3p;
    __half *p_hwh, *p_xh, *p_hh, *p_w1h, *p_w2h, *p_w3h;
    cudaGetSymbolAddress((void**)&p_hwh, g_hwh);
    cudaGetSymbolAddress((void**)&p_acc, g_acc);
    cudaGetSymbolAddress((void**)&p_b3p, g_b3p);
    cudaGetSymbolAddress((void**)&p_xh,  g_xh);
    cudaGetSymbolAddress((void**)&p_hh,  g_hh);
    cudaGetSymbolAddress((void**)&p_w1h, g_w1h);
    cudaGetSymbolAddress((void**)&p_w2h, g_w2h);
    cudaGetSymbolAddress((void**)&p_w3h, g_w3h);

    const int GSMEM = 2 * 2 * 128 * 80;  // 40960 bytes

    static cudaStream_t s2 = nullptr;
    static cudaEvent_t ev_fork = nullptr, ev_join = nullptr;
    if (s2 == nullptr) {
        cudaStreamCreateWithFlags(&s2, cudaStreamNonBlocking);
        cudaEventCreateWithFlags(&ev_fork, cudaEventDisableTiming);
        cudaEventCreateWithFlags(&ev_join, cudaEventDisableTiming);
    }

    const int TPB = 256;
    const int GRID_M = (NN + 127) / 128;           // 391
    const int GRID_W = (NN * 32 + TPB - 1) / TPB;

    // ---- fork: CSR build chain + later-layer weight prep on side stream ----
    cudaEventRecord(ev_fork, 0);
    cudaStreamWaitEvent(s2, ev_fork, 0);
    zero_dc_kernel<<<(NN + TPB - 1) / TPB, TPB, 0, s2>>>();
    count_deg_kernel<<<(EE + TPB - 1) / TPB, TPB, 0, s2>>>(dst, ew, EE);
    blocksum_dinv_kernel<<<NBLK, SCAN_B, 0, s2>>>();
    scatter_rowptr_kernel<<<NBLK, SCAN_B, 0, s2>>>();
    fill_kernel<<<(EE + TPB - 1) / TPB, TPB, 0, s2>>>(src, dst, ew, EE);
    prep_w_kernel<<<(2 * 128 * 128 + TPB - 1) / TPB, TPB, 0, s2>>>(wg2, ws2, 128, 128, 128, p_w2h);
    prep_w_kernel<<<(2 * 64 * 128 + TPB - 1) / TPB, TPB, 0, s2>>>(wg3, ws3, 128, 40, 64, p_w3h);
    prep_b3_kernel<<<1, 64, 0, s2>>>(b3);
    cudaEventRecord(ev_join, s2);

    // ---- main stream: only what gates layer-1 GEMM ----
    prep_w_kernel<<<(2 * 128 * 256 + TPB - 1) / TPB, TPB>>>(wg1, ws1, 256, 128, 128, p_w1h);
    split_kernel<<<(NN * F_IN + TPB - 1) / TPB, TPB>>>(x, p_xh, NN * F_IN);
    gcn_gemm_mma<256, 128><<<dim3(GRID_M, 2), 256, GSMEM>>>(p_xh, p_w1h, b1, p_hwh, p_acc, NN);

    // ---- join ----
    cudaStreamWaitEvent(0, ev_join, 0);
    agg_bn12_kernel<<<GRID_W, TPB>>>(p_hwh, p_acc, gm1, bt1, mn1, vr1, p_hh);

    // ---- layer 2 ----
    gcn_gemm_mma<128, 128><<<dim3(GRID_M, 2), 256, GSMEM>>>(p_hh, p_w2h, b2, p_hwh, p_acc, NN);
    agg_bn12_kernel<<<GRID_W, TPB>>>(p_hwh, p_acc, gm2, bt2, mn2, vr2, p_hh);

    // ---- layer 3 ----
    gcn_gemm_mma<128, 64><<<dim3(GRID_M, 1), 256, GSMEM>>>(p_hh, p_w3h, p_b3p, p_hwh, p_acc, NN);
    agg_bn3_kernel<<<GRID_W, TPB>>>(p_hwh, p_acc, gm3, bt3, mn3, vr3, out);
}

// round 15
// speedup vs baseline: 1.1260x; 1.0118x over previous
#include <cuda_runtime.h>
#include <cuda_bf16.h>
#include <cuda_fp16.h>
#include <cstdint>

// Problem constants
#define NN 50000
#define EE 1000000
#define F_IN 256
#define UNITS 128
#define NCLS 40
#define NCLS_PAD 64
#define EPSBN 1e-3f

#define SCAN_B 256
#define NBLK ((NN + SCAN_B - 1) / SCAN_B)   // 196

// ================= mma.sync / cp.async helpers =================
__device__ __forceinline__ uint32_t smem_to_u32(const void* p) {
    uint32_t a;
    asm("{ .reg .u64 t; cvta.to.shared.u64 t, %1; cvt.u32.u64 %0, t; }" : "=r"(a) : "l"(p));
    return a;
}
#define LDSM_X4(r, addr) \
    asm volatile("ldmatrix.sync.aligned.m8n8.x4.shared.b16 {%0,%1,%2,%3}, [%4];" \
        : "=r"((r)[0]), "=r"((r)[1]), "=r"((r)[2]), "=r"((r)[3]) : "r"(addr))
#define LDSM_X2(r, addr) \
    asm volatile("ldmatrix.sync.aligned.m8n8.x2.shared.b16 {%0,%1}, [%2];" \
        : "=r"((r)[0]), "=r"((r)[1]) : "r"(addr))

__device__ __forceinline__ void mma_f16(float* c, const uint32_t* a, const uint32_t* b) {
    asm volatile("mma.sync.aligned.m16n8k16.row.col.f32.f16.f16.f32 "
        "{%0,%1,%2,%3}, {%4,%5,%6,%7}, {%8,%9}, {%0,%1,%2,%3};"
        : "+f"(c[0]), "+f"(c[1]), "+f"(c[2]), "+f"(c[3])
        : "r"(a[0]), "r"(a[1]), "r"(a[2]), "r"(a[3]), "r"(b[0]), "r"(b[1]));
}
__device__ __forceinline__ void cp_async16(uint32_t sa, const void* g, uint32_t pbytes) {
    asm volatile("cp.async.cg.shared.global [%0], [%1], 16, %2;"
                 :: "r"(sa), "l"(g), "r"(pbytes) : "memory");
}
#define CP_COMMIT() asm volatile("cp.async.commit_group;" ::: "memory")
#define CP_WAIT0()  asm volatile("cp.async.wait_group 0;" ::: "memory")
#define CP_WAIT1()  asm volatile("cp.async.wait_group 1;" ::: "memory")

// ================= scratch (static device globals) =================
__device__ __align__(16) float g_deg[NN];
__device__ __align__(16) int   g_cnt[NN];
__device__ __align__(16) int   g_rowptr[NN + 1];
__device__ __align__(16) int   g_bsum[NBLK];
__device__ __align__(16) uint2 g_edge[EE];                 // packed (src, norm_w)
__device__ __align__(16) __half g_hwh[(size_t)NN * 128];   // fp16 gcn-path GEMM output
__device__ __align__(16) __half g_acch[(size_t)NN * 128];  // fp16 self path (+bias)
__device__ __align__(16) __half g_xh[(size_t)NN * F_IN];   // fp16 input features
__device__ __align__(16) __half g_hh[(size_t)NN * 128];    // fp16 layer activations
__device__ __align__(16) __half g_w1h[256 * 256];
__device__ __align__(16) __half g_w2h[256 * 128];
__device__ __align__(16) __half g_w3h[128 * 128];
__device__ __align__(16) float g_b3p[NCLS_PAD];

// ================= CSR build =================
__global__ void zero_dc_kernel() {
    int i = blockIdx.x * blockDim.x + threadIdx.x;
    if (i < NN) { g_deg[i] = 0.f; g_cnt[i] = 0; }
}
__global__ void count_deg_kernel(const int* __restrict__ dst, const float* __restrict__ w, int e) {
    int i = blockIdx.x * blockDim.x + threadIdx.x;
    if (i < e) {
        int d = dst[i];
        atomicAdd(&g_cnt[d], 1);
        atomicAdd(&g_deg[d], w[i]);
    }
}
__global__ void __launch_bounds__(SCAN_B) blocksum_dinv_kernel() {
    __shared__ int sh[SCAN_B];
    int i = blockIdx.x * SCAN_B + threadIdx.x;
    int v = 0;
    if (i < NN) {
        v = g_cnt[i];
        float d = g_deg[i];
        g_deg[i] = (d > 0.f) ? rsqrtf(d) : 0.f;
    }
    sh[threadIdx.x] = v;
    __syncthreads();
    for (int off = SCAN_B / 2; off > 0; off >>= 1) {
        if (threadIdx.x < off) sh[threadIdx.x] += sh[threadIdx.x + off];
        __syncthreads();
    }
    if (threadIdx.x == 0) g_bsum[blockIdx.x] = sh[0];
}
__global__ void __launch_bounds__(SCAN_B) scatter_rowptr_kernel() {
    __shared__ int sh[SCAN_B];
    __shared__ int red[SCAN_B];
    int i = blockIdx.x * SCAN_B + threadIdx.x;
    int t = threadIdx.x;
    int bv = (t < NBLK) ? g_bsum[t] : 0;
    red[t] = (t < blockIdx.x) ? bv : 0;
    sh[t] = bv;
    __syncthreads();
    for (int off = SCAN_B / 2; off > 0; off >>= 1) {
        if (t < off) { red[t] += red[t + off]; sh[t] += sh[t + off]; }
        __syncthreads();
    }
    int boff = red[0];
    int total = sh[0];
    __syncthreads();
    int v = (i < NN) ? g_cnt[i] : 0;
    sh[t] = v;
    __syncthreads();
    for (int off = 1; off < SCAN_B; off <<= 1) {
        int u = (t >= off) ? sh[t - off] : 0;
        __syncthreads();
        sh[t] += u;
        __syncthreads();
    }
    if (i < NN) {
        g_rowptr[i] = boff + sh[t] - v;
        g_cnt[i] = 0;
    }
    if (blockIdx.x == NBLK - 1 && t == 0) g_rowptr[NN] = total;
}
__global__ void fill_kernel(const int* __restrict__ src, const int* __restrict__ dst,
                            const float* __restrict__ w, int e) {
    int i = blockIdx.x * blockDim.x + threadIdx.x;
    if (i >= e) return;
    int s = src[i], d = dst[i];
    int pos = g_rowptr[d] + atomicAdd(&g_cnt[d], 1);
    float nw = g_deg[s] * w[i] * g_deg[d];
    g_edge[pos] = make_uint2((uint32_t)s, __float_as_uint(nw));
}

// ================= prep kernels =================
__global__ void prep_w_kernel(const float* __restrict__ Wg, const float* __restrict__ Ws,
                              int K, int NV, int NHALF, __half* __restrict__ wout) {
    int idx = blockIdx.x * blockDim.x + threadIdx.x;
    int total = 2 * NHALF * K;
    if (idx >= total) return;
    int n = idx / K, k = idx - n * K;
    float v = 0.f;
    if (n < NHALF) { if (n < NV) v = Wg[k * NV + n]; }
    else { int c = n - NHALF; if (c < NV) v = Ws[k * NV + c]; }
    wout[idx] = __float2half_rn(v);
}
__global__ void prep_b3_kernel(const float* __restrict__ b) {
    int i = threadIdx.x;
    if (i < NCLS_PAD) g_b3p[i] = (i < NCLS) ? b[i] : 0.f;
}
__global__ void split_kernel(const float* __restrict__ in, __half* __restrict__ o, int n) {
    int i = blockIdx.x * blockDim.x + threadIdx.x;
    if (i < n) o[i] = __float2half_rn(in[i]);
}

// ================= cp.async double-buffered fp16 GEMM; 2 CTAs/SM; fp16 outputs =================
template<int K, int NHALF>
__global__ void __launch_bounds__(256, 2) gcn_gemm_mma(
    const __half* __restrict__ A, const __half* __restrict__ W,
    const float* __restrict__ bias,
    __half* __restrict__ out_gcn, __half* __restrict__ out_self, int nrows)
{
    constexpr int BK = 32;
    constexpr int NIT = K / BK;
    constexpr int ROWB = 80;
    constexpr int TILE = 128 * ROWB;
    constexpr int STAGE = 2 * TILE;

    extern __shared__ __align__(16) unsigned char sm[];

    const int tid = threadIdx.x;
    const int lane = tid & 31;
    const int wid = tid >> 5;
    const int row0 = blockIdx.x * 128;
    const int n0 = blockIdx.y * 128;
    const uint32_t sbase = smem_to_u32(sm);

    const int wm = wid >> 2;
    const int wn = wid & 3;
    const int m0w = wm * 64;
    const int n0w = wn * 32;

    float acc[4][4][4];
#pragma unroll
    for (int mt = 0; mt < 4; mt++)
#pragma unroll
        for (int nt = 0; nt < 4; nt++)
#pragma unroll
            for (int j = 0; j < 4; j++) acc[mt][nt][j] = 0.f;

    auto load_stage = [&](int kc, int st) {
#pragma unroll
        for (int t = 0; t < 2; t++) {
            int i = tid + t * 256;
            int r = i >> 2, q = i & 3;
            size_t gcol = (size_t)kc * BK + q * 8;
            uint32_t sa = sbase + st * STAGE + (uint32_t)(r * ROWB + q * 16);
            int grow = row0 + r;
            uint32_t pb = (grow < nrows) ? 16u : 0u;
            int gr = (grow < nrows) ? grow : 0;
            cp_async16(sa,        A + (size_t)gr * K + gcol, pb);
            int brow = n0 + r;
            cp_async16(sa + TILE, W + (size_t)brow * K + gcol, 16u);
        }
    };

    load_stage(0, 0);
    CP_COMMIT();

    for (int kc = 0; kc < NIT; kc++) {
        if (kc + 1 < NIT) {
            load_stage(kc + 1, (kc + 1) & 1);
            CP_COMMIT();
            CP_WAIT1();
        } else {
            CP_WAIT0();
        }
        __syncthreads();

        uint32_t stoff = (uint32_t)((kc & 1) * STAGE);
#pragma unroll
        for (int ks = 0; ks < 2; ks++) {
            uint32_t ah[4][4], bh[4][2];
#pragma unroll
            for (int mt = 0; mt < 4; mt++) {
                uint32_t addr = sbase + stoff +
                    (uint32_t)((m0w + mt * 16 + (lane & 15)) * ROWB + (ks * 2 + (lane >> 4)) * 16);
                LDSM_X4(ah[mt], addr);
            }
#pragma unroll
            for (int nt = 0; nt < 4; nt++) {
                uint32_t addr = sbase + stoff + TILE +
                    (uint32_t)((n0w + nt * 8 + (lane & 7)) * ROWB + (ks * 2 + ((lane >> 3) & 1)) * 16);
                LDSM_X2(bh[nt], addr);
            }
#pragma unroll
            for (int mt = 0; mt < 4; mt++)
#pragma unroll
                for (int nt = 0; nt < 4; nt++)
                    mma_f16(acc[mt][nt], ah[mt], bh[nt]);
        }
        __syncthreads();
    }

#pragma unroll
    for (int mt = 0; mt < 4; mt++) {
        int rlo = row0 + m0w + mt * 16 + (lane >> 2);
        int rhi = rlo + 8;
#pragma unroll
        for (int nt = 0; nt < 4; nt++) {
            int gn = n0 + n0w + nt * 8 + (lane & 3) * 2;
            bool isg = gn < NHALF;
            int col = isg ? gn : gn - NHALF;
            if (isg) {
                if (rlo < nrows)
                    *reinterpret_cast<__half2*>(out_gcn + (size_t)rlo * NHALF + col) =
                        __floats2half2_rn(acc[mt][nt][0], acc[mt][nt][1]);
                if (rhi < nrows)
                    *reinterpret_cast<__half2*>(out_gcn + (size_t)rhi * NHALF + col) =
                        __floats2half2_rn(acc[mt][nt][2], acc[mt][nt][3]);
            } else {
                float bx = __ldg(&bias[col]), by = __ldg(&bias[col + 1]);
                if (rlo < nrows)
                    *reinterpret_cast<__half2*>(out_self + (size_t)rlo * NHALF + col) =
                        __floats2half2_rn(acc[mt][nt][0] + bx, acc[mt][nt][1] + by);
                if (rhi < nrows)
                    *reinterpret_cast<__half2*>(out_self + (size_t)rhi * NHALF + col) =
                        __floats2half2_rn(acc[mt][nt][2] + bx, acc[mt][nt][3] + by);
            }
        }
    }
}

// ================= CSR aggregation + BN fused (packed edges, 4x unrolled) =================
__global__ void __launch_bounds__(256) agg_bn12_kernel(
    const __half* __restrict__ hw, const __half* __restrict__ selfacc,
    const float* __restrict__ gamma, const float* __restrict__ beta,
    const float* __restrict__ mean, const float* __restrict__ var,
    __half* __restrict__ hout)
{
    int v = (blockIdx.x * blockDim.x + threadIdx.x) >> 5;
    if (v >= NN) return;
    int lane = threadIdx.x & 31;
    int beg = g_rowptr[v], end = g_rowptr[v + 1];

    float4 acc = make_float4(0.f, 0.f, 0.f, 0.f);
    int e = beg;
    for (; e + 3 < end; e += 4) {
        uint2 er[4];
        uint2 u[4];
#pragma unroll
        for (int q = 0; q < 4; q++) er[q] = __ldg(&g_edge[e + q]);
#pragma unroll
        for (int q = 0; q < 4; q++)
            u[q] = __ldg(reinterpret_cast<const uint2*>(hw + (size_t)er[q].x * 128) + lane);
#pragma unroll
        for (int q = 0; q < 4; q++) {
            float w = __uint_as_float(er[q].y);
            float2 a = __half22float2(*reinterpret_cast<__half2*>(&u[q].x));
            float2 b = __half22float2(*reinterpret_cast<__half2*>(&u[q].y));
            acc.x += w * a.x;
            acc.y += w * a.y;
            acc.z += w * b.x;
            acc.w += w * b.y;
        }
    }
    for (; e < end; e++) {
        uint2 e0 = __ldg(&g_edge[e]);
        float w0 = __uint_as_float(e0.y);
        uint2 u0 = __ldg(reinterpret_cast<const uint2*>(hw + (size_t)e0.x * 128) + lane);
        float2 a0 = __half22float2(*reinterpret_cast<__half2*>(&u0.x));
        float2 b0 = __half22float2(*reinterpret_cast<__half2*>(&u0.y));
        acc.x += w0 * a0.x; acc.y += w0 * a0.y; acc.z += w0 * b0.x; acc.w += w0 * b0.y;
    }

    uint2 su = __ldg(reinterpret_cast<const uint2*>(selfacc + (size_t)v * 128) + lane);
    float2 s0 = __half22float2(*reinterpret_cast<__half2*>(&su.x));
    float2 s1 = __half22float2(*reinterpret_cast<__half2*>(&su.y));
    int c = lane * 4;
    float vals[4] = { acc.x + s0.x, acc.y + s0.y, acc.z + s1.x, acc.w + s1.y };
#pragma unroll
    for (int j = 0; j < 4; j++) {
        int ch = c + j;
        float t = vals[j];
        t = (t - __ldg(&mean[ch])) * rsqrtf(__ldg(&var[ch]) + EPSBN) * __ldg(&gamma[ch]) + __ldg(&beta[ch]);
        vals[j] = fmaxf(t, 0.f);
    }
    __half2 p0 = __floats2half2_rn(vals[0], vals[1]);
    __half2 p1 = __floats2half2_rn(vals[2], vals[3]);
    uint2 pk;
    pk.x = *reinterpret_cast<uint32_t*>(&p0);
    pk.y = *reinterpret_cast<uint32_t*>(&p1);
    *reinterpret_cast<uint2*>(hout + (size_t)v * 128 + c) = pk;
}

__global__ void __launch_bounds__(256) agg_bn3_kernel(
    const __half* __restrict__ hw, const __half* __restrict__ selfacc,
    const float* __restrict__ gamma, const float* __restrict__ beta,
    const float* __restrict__ mean, const float* __restrict__ var,
    float* __restrict__ out)
{
    int v = (blockIdx.x * blockDim.x + threadIdx.x) >> 5;
    if (v >= NN) return;
    int lane = threadIdx.x & 31;
    if (lane >= 20) return;
    int beg = g_rowptr[v], end = g_rowptr[v + 1];

    float2 acc = make_float2(0.f, 0.f);
    int e = beg;
    for (; e + 3 < end; e += 4) {
        uint2 e0 = __ldg(&g_edge[e]);
        uint2 e1 = __ldg(&g_edge[e + 1]);
        uint2 e2 = __ldg(&g_edge[e + 2]);
        uint2 e3 = __ldg(&g_edge[e + 3]);
        uint u0 = __ldg(reinterpret_cast<const uint32_t*>(hw + (size_t)e0.x * NCLS_PAD) + lane);
        uint u1 = __ldg(reinterpret_cast<const uint32_t*>(hw + (size_t)e1.x * NCLS_PAD) + lane);
        uint u2 = __ldg(reinterpret_cast<const uint32_t*>(hw + (size_t)e2.x * NCLS_PAD) + lane);
        uint u3 = __ldg(reinterpret_cast<const uint32_t*>(hw + (size_t)e3.x * NCLS_PAD) + lane);
        float2 f0 = __half22float2(*reinterpret_cast<__half2*>(&u0));
        float2 f1 = __half22float2(*reinterpret_cast<__half2*>(&u1));
        float2 f2 = __half22float2(*reinterpret_cast<__half2*>(&u2));
        float2 f3 = __half22float2(*reinterpret_cast<__half2*>(&u3));
        float w0 = __uint_as_float(e0.y), w1 = __uint_as_float(e1.y);
        float w2 = __uint_as_float(e2.y), w3 = __uint_as_float(e3.y);
        acc.x += w0 * f0.x + w1 * f1.x + w2 * f2.x + w3 * f3.x;
        acc.y += w0 * f0.y + w1 * f1.y + w2 * f2.y + w3 * f3.y;
    }
    for (; e < end; e++) {
        uint2 e0 = __ldg(&g_edge[e]);
        float w0 = __uint_as_float(e0.y);
        uint u0 = __ldg(reinterpret_cast<const uint32_t*>(hw + (size_t)e0.x * NCLS_PAD) + lane);
        float2 f0 = __half22float2(*reinterpret_cast<__half2*>(&u0));
        acc.x += w0 * f0.x;
        acc.y += w0 * f0.y;
    }

    uint su = __ldg(reinterpret_cast<const uint32_t*>(selfacc + (size_t)v * NCLS_PAD) + lane);
    float2 sf = __half22float2(*reinterpret_cast<__half2*>(&su));
    int c = lane * 2;
    float2 o;
    o.x = (acc.x + sf.x - __ldg(&mean[c]))     * rsqrtf(__ldg(&var[c]) + EPSBN)     * __ldg(&gamma[c])     + __ldg(&beta[c]);
    o.y = (acc.y + sf.y - __ldg(&mean[c + 1])) * rsqrtf(__ldg(&var[c + 1]) + EPSBN) * __ldg(&gamma[c + 1]) + __ldg(&beta[c + 1]);
    *reinterpret_cast<float2*>(out + (size_t)v * NCLS + c) = o;
}

// ================= launch =================
extern "C" void kernel_launch(void* const* d_in, const int* in_sizes, int n_in,
                              void* d_out, int out_size) {
    const float* x   = (const float*)d_in[0];
    const int*   ei  = (const int*)d_in[1];
    const float* ew  = (const float*)d_in[2];
    const int* src = ei;
    const int* dst = ei + EE;

    const float* wg1 = (const float*)d_in[3];
    const float* ws1 = (const float*)d_in[4];
    const float* b1  = (const float*)d_in[5];
    const float* gm1 = (const float*)d_in[6];
    const float* bt1 = (const float*)d_in[7];
    const float* mn1 = (const float*)d_in[8];
    const float* vr1 = (const float*)d_in[9];

    const float* wg2 = (const float*)d_in[10];
    const float* ws2 = (const float*)d_in[11];
    const float* b2  = (const float*)d_in[12];
    const float* gm2 = (const float*)d_in[13];
    const float* bt2 = (const float*)d_in[14];
    const float* mn2 = (const float*)d_in[15];
    const float* vr2 = (const float*)d_in[16];

    const float* wg3 = (const float*)d_in[17];
    const float* ws3 = (const float*)d_in[18];
    const float* b3  = (const float*)d_in[19];
    const float* gm3 = (const float*)d_in[20];
    const float* bt3 = (const float*)d_in[21];
    const float* mn3 = (const float*)d_in[22];
    const float* vr3 = (const float*)d_in[23];

    float* out = (float*)d_out;

    float* p_b3p;
    __half *p_hwh, *p_acch, *p_xh, *p_hh, *p_w1h, *p_w2h, *p_w3h;
    cudaGetSymbolAddress((void**)&p_hwh,  g_hwh);
    cudaGetSymbolAddress((void**)&p_acch, g_acch);
    cudaGetSymbolAddress((void**)&p_b3p,  g_b3p);
    cudaGetSymbolAddress((void**)&p_xh,   g_xh);
    cudaGetSymbolAddress((void**)&p_hh,   g_hh);
    cudaGetSymbolAddress((void**)&p_w1h,  g_w1h);
    cudaGetSymbolAddress((void**)&p_w2h,  g_w2h);
    cudaGetSymbolAddress((void**)&p_w3h,  g_w3h);

    const int GSMEM = 2 * 2 * 128 * 80;  // 40960 bytes

    static cudaStream_t s2 = nullptr;
    static cudaEvent_t ev_fork = nullptr, ev_join = nullptr;
    if (s2 == nullptr) {
        cudaStreamCreateWithFlags(&s2, cudaStreamNonBlocking);
        cudaEventCreateWithFlags(&ev_fork, cudaEventDisableTiming);
        cudaEventCreateWithFlags(&ev_join, cudaEventDisableTiming);
    }

    const int TPB = 256;
    const int GRID_M = (NN + 127) / 128;           // 391
    const int GRID_W = (NN * 32 + TPB - 1) / TPB;

    // ---- fork: CSR build chain + later-layer weight prep on side stream ----
    cudaEventRecord(ev_fork, 0);
    cudaStreamWaitEvent(s2, ev_fork, 0);
    zero_dc_kernel<<<(NN + TPB - 1) / TPB, TPB, 0, s2>>>();
    count_deg_kernel<<<(EE + TPB - 1) / TPB, TPB, 0, s2>>>(dst, ew, EE);
    blocksum_dinv_kernel<<<NBLK, SCAN_B, 0, s2>>>();
    scatter_rowptr_kernel<<<NBLK, SCAN_B, 0, s2>>>();
    fill_kernel<<<(EE + TPB - 1) / TPB, TPB, 0, s2>>>(src, dst, ew, EE);
    prep_w_kernel<<<(2 * 128 * 128 + TPB - 1) / TPB, TPB, 0, s2>>>(wg2, ws2, 128, 128, 128, p_w2h);
    prep_w_kernel<<<(2 * 64 * 128 + TPB - 1) / TPB, TPB, 0, s2>>>(wg3, ws3, 128, 40, 64, p_w3h);
    prep_b3_kernel<<<1, 64, 0, s2>>>(b3);
    cudaEventRecord(ev_join, s2);

    // ---- main stream: only what gates layer-1 GEMM ----
    prep_w_kernel<<<(2 * 128 * 256 + TPB - 1) / TPB, TPB>>>(wg1, ws1, 256, 128, 128, p_w1h);
    split_kernel<<<(NN * F_IN + TPB - 1) / TPB, TPB>>>(x, p_xh, NN * F_IN);
    gcn_gemm_mma<256, 128><<<dim3(GRID_M, 2), 256, GSMEM>>>(p_xh, p_w1h, b1, p_hwh, p_acch, NN);

    // ---- join ----
    cudaStreamWaitEvent(0, ev_join, 0);
    agg_bn12_kernel<<<GRID_W, TPB>>>(p_hwh, p_acch, gm1, bt1, mn1, vr1, p_hh);

    // ---- layer 2 ----
    gcn_gemm_mma<128, 128><<<dim3(GRID_M, 2), 256, GSMEM>>>(p_hh, p_w2h, b2, p_hwh, p_acch, NN);
    agg_bn12_kernel<<<GRID_W, TPB>>>(p_hwh, p_acch, gm2, bt2, mn2, vr2, p_hh);

    // ---- layer 3 ----
    gcn_gemm_mma<128, 64><<<dim3(GRID_M, 1), 256, GSMEM>>>(p_hh, p_w3h, p_b3p, p_hwh, p_acch, NN);
    agg_bn3_kernel<<<GRID_W, TPB>>>(p_hwh, p_acch, gm3, bt3, mn3, vr3, out);
}

// round 16
// speedup vs baseline: 1.3076x; 1.1613x over previous
#include <cuda_runtime.h>
#include <cuda_bf16.h>
#include <cuda_fp16.h>
#include <cstdint>

// Problem constants
#define NN 50000
#define EE 1000000
#define F_IN 256
#define UNITS 128
#define NCLS 40
#define NCLS_PAD 64
#define EPSBN 1e-3f

#define SCAN_B 256
#define NBLK ((NN + SCAN_B - 1) / SCAN_B)   // 196

// ================= mma.sync / cp.async helpers =================
__device__ __forceinline__ uint32_t smem_to_u32(const void* p) {
    uint32_t a;
    asm("{ .reg .u64 t; cvta.to.shared.u64 t, %1; cvt.u32.u64 %0, t; }" : "=r"(a) : "l"(p));
    return a;
}
#define LDSM_X4(r, addr) \
    asm volatile("ldmatrix.sync.aligned.m8n8.x4.shared.b16 {%0,%1,%2,%3}, [%4];" \
        : "=r"((r)[0]), "=r"((r)[1]), "=r"((r)[2]), "=r"((r)[3]) : "r"(addr))
#define LDSM_X2(r, addr) \
    asm volatile("ldmatrix.sync.aligned.m8n8.x2.shared.b16 {%0,%1}, [%2];" \
        : "=r"((r)[0]), "=r"((r)[1]) : "r"(addr))

__device__ __forceinline__ void mma_f16(float* c, const uint32_t* a, const uint32_t* b) {
    asm volatile("mma.sync.aligned.m16n8k16.row.col.f32.f16.f16.f32 "
        "{%0,%1,%2,%3}, {%4,%5,%6,%7}, {%8,%9}, {%0,%1,%2,%3};"
        : "+f"(c[0]), "+f"(c[1]), "+f"(c[2]), "+f"(c[3])
        : "r"(a[0]), "r"(a[1]), "r"(a[2]), "r"(a[3]), "r"(b[0]), "r"(b[1]));
}
__device__ __forceinline__ void cp_async16(uint32_t sa, const void* g, uint32_t pbytes) {
    asm volatile("cp.async.cg.shared.global [%0], [%1], 16, %2;"
                 :: "r"(sa), "l"(g), "r"(pbytes) : "memory");
}
#define CP_COMMIT() asm volatile("cp.async.commit_group;" ::: "memory")
#define CP_WAIT0()  asm volatile("cp.async.wait_group 0;" ::: "memory")
#define CP_WAIT1()  asm volatile("cp.async.wait_group 1;" ::: "memory")
#define STS128(sa, a, b, c, d) \
    asm volatile("st.shared.v4.b32 [%0], {%1, %2, %3, %4};" \
        :: "r"(sa), "r"(a), "r"(b), "r"(c), "r"(d) : "memory")

// ================= scratch (static device globals) =================
__device__ __align__(16) float g_deg[NN];
__device__ __align__(16) int   g_cnt[NN];
__device__ __align__(16) int   g_rowptr[NN + 1];
__device__ __align__(16) int   g_bsum[NBLK];
__device__ __align__(16) uint2 g_edge[EE];                 // packed (src, norm_w)
__device__ __align__(16) __half g_hwh[(size_t)NN * 128];   // fp16 gcn-path GEMM output
__device__ __align__(16) __half g_acch[(size_t)NN * 128];  // fp16 self path (+bias)
__device__ __align__(16) __half g_hh[(size_t)NN * 128];    // fp16 layer activations
__device__ __align__(16) __half g_w1h[256 * 256];
__device__ __align__(16) __half g_w2h[256 * 128];
__device__ __align__(16) __half g_w3h[128 * 128];
__device__ __align__(16) float g_b3p[NCLS_PAD];

// ================= CSR build =================
__global__ void zero_dc_kernel() {
    int i = blockIdx.x * blockDim.x + threadIdx.x;
    if (i < NN) { g_deg[i] = 0.f; g_cnt[i] = 0; }
}
__global__ void count_deg_kernel(const int* __restrict__ dst, const float* __restrict__ w, int e) {
    int i = blockIdx.x * blockDim.x + threadIdx.x;
    if (i < e) {
        int d = dst[i];
        atomicAdd(&g_cnt[d], 1);
        atomicAdd(&g_deg[d], w[i]);
    }
}
__global__ void __launch_bounds__(SCAN_B) blocksum_dinv_kernel() {
    __shared__ int sh[SCAN_B];
    int i = blockIdx.x * SCAN_B + threadIdx.x;
    int v = 0;
    if (i < NN) {
        v = g_cnt[i];
        float d = g_deg[i];
        g_deg[i] = (d > 0.f) ? rsqrtf(d) : 0.f;
    }
    sh[threadIdx.x] = v;
    __syncthreads();
    for (int off = SCAN_B / 2; off > 0; off >>= 1) {
        if (threadIdx.x < off) sh[threadIdx.x] += sh[threadIdx.x + off];
        __syncthreads();
    }
    if (threadIdx.x == 0) g_bsum[blockIdx.x] = sh[0];
}
__global__ void __launch_bounds__(SCAN_B) scatter_rowptr_kernel() {
    __shared__ int sh[SCAN_B];
    __shared__ int red[SCAN_B];
    int i = blockIdx.x * SCAN_B + threadIdx.x;
    int t = threadIdx.x;
    int bv = (t < NBLK) ? g_bsum[t] : 0;
    red[t] = (t < blockIdx.x) ? bv : 0;
    sh[t] = bv;
    __syncthreads();
    for (int off = SCAN_B / 2; off > 0; off >>= 1) {
        if (t < off) { red[t] += red[t + off]; sh[t] += sh[t + off]; }
        __syncthreads();
    }
    int boff = red[0];
    int total = sh[0];
    __syncthreads();
    int v = (i < NN) ? g_cnt[i] : 0;
    sh[t] = v;
    __syncthreads();
    for (int off = 1; off < SCAN_B; off <<= 1) {
        int u = (t >= off) ? sh[t - off] : 0;
        __syncthreads();
        sh[t] += u;
        __syncthreads();
    }
    if (i < NN) {
        g_rowptr[i] = boff + sh[t] - v;
        g_cnt[i] = 0;
    }
    if (blockIdx.x == NBLK - 1 && t == 0) g_rowptr[NN] = total;
}
__global__ void fill_kernel(const int* __restrict__ src, const int* __restrict__ dst,
                            const float* __restrict__ w, int e) {
    int i = blockIdx.x * blockDim.x + threadIdx.x;
    if (i >= e) return;
    int s = src[i], d = dst[i];
    int pos = g_rowptr[d] + atomicAdd(&g_cnt[d], 1);
    float nw = g_deg[s] * w[i] * g_deg[d];
    g_edge[pos] = make_uint2((uint32_t)s, __float_as_uint(nw));
}

// ================= prep kernels =================
__global__ void prep_w_kernel(const float* __restrict__ Wg, const float* __restrict__ Ws,
                              int K, int NV, int NHALF, __half* __restrict__ wout) {
    int idx = blockIdx.x * blockDim.x + threadIdx.x;
    int total = 2 * NHALF * K;
    if (idx >= total) return;
    int n = idx / K, k = idx - n * K;
    float v = 0.f;
    if (n < NHALF) { if (n < NV) v = Wg[k * NV + n]; }
    else { int c = n - NHALF; if (c < NV) v = Ws[k * NV + c]; }
    wout[idx] = __float2half_rn(v);
}
__global__ void prep_b3_kernel(const float* __restrict__ b) {
    int i = threadIdx.x;
    if (i < NCLS_PAD) g_b3p[i] = (i < NCLS) ? b[i] : 0.f;
}

// ======= cp.async double-buffered fp16 GEMM; optional fused fp32->fp16 A-load =======
template<int K, int NHALF, bool CONV>
__global__ void __launch_bounds__(256, 2) gcn_gemm_mma(
    const void* __restrict__ Av, const __half* __restrict__ W,
    const float* __restrict__ bias,
    __half* __restrict__ out_gcn, __half* __restrict__ out_self, int nrows)
{
    constexpr int BK = 32;
    constexpr int NIT = K / BK;
    constexpr int ROWB = 80;
    constexpr int TILE = 128 * ROWB;
    constexpr int STAGE = 2 * TILE;

    extern __shared__ __align__(16) unsigned char sm[];

    const __half* Ah = (const __half*)Av;
    const float*  Af = (const float*)Av;

    const int tid = threadIdx.x;
    const int lane = tid & 31;
    const int wid = tid >> 5;
    const int row0 = blockIdx.x * 128;
    const int n0 = blockIdx.y * 128;
    const uint32_t sbase = smem_to_u32(sm);

    const int wm = wid >> 2;
    const int wn = wid & 3;
    const int m0w = wm * 64;
    const int n0w = wn * 32;

    float acc[4][4][4];
#pragma unroll
    for (int mt = 0; mt < 4; mt++)
#pragma unroll
        for (int nt = 0; nt < 4; nt++)
#pragma unroll
            for (int j = 0; j < 4; j++) acc[mt][nt][j] = 0.f;

    float abuf[2][16];  // CONV A prefetch buffers (unused -> eliminated)

    auto load_W = [&](int kc, int st) {
#pragma unroll
        for (int t = 0; t < 2; t++) {
            int i = tid + t * 256;
            int r = i >> 2, q = i & 3;
            size_t gcol = (size_t)kc * BK + q * 8;
            uint32_t sa = sbase + st * STAGE + TILE + (uint32_t)(r * ROWB + q * 16);
            int brow = n0 + r;
            cp_async16(sa, W + (size_t)brow * K + gcol, 16u);
        }
    };
    auto load_A_async = [&](int kc, int st) {
#pragma unroll
        for (int t = 0; t < 2; t++) {
            int i = tid + t * 256;
            int r = i >> 2, q = i & 3;
            size_t gcol = (size_t)kc * BK + q * 8;
            uint32_t sa = sbase + st * STAGE + (uint32_t)(r * ROWB + q * 16);
            int grow = row0 + r;
            uint32_t pb = (grow < nrows) ? 16u : 0u;
            int gr = (grow < nrows) ? grow : 0;
            cp_async16(sa, Ah + (size_t)gr * K + gcol, pb);
        }
    };
    auto ldg_A = [&](int kc, float* dstb) {
#pragma unroll
        for (int t = 0; t < 2; t++) {
            int i = tid + t * 256;
            int r = i >> 2, q = i & 3;
            int grow = row0 + r;
            float4 v0 = make_float4(0.f, 0.f, 0.f, 0.f), v1 = v0;
            if (grow < nrows) {
                const float4* p = reinterpret_cast<const float4*>(
                    Af + (size_t)grow * K + (size_t)kc * BK + q * 8);
                v0 = __ldg(p);
                v1 = __ldg(p + 1);
            }
            float* d = dstb + t * 8;
            d[0] = v0.x; d[1] = v0.y; d[2] = v0.z; d[3] = v0.w;
            d[4] = v1.x; d[5] = v1.y; d[6] = v1.z; d[7] = v1.w;
        }
    };
    auto sts_A = [&](int st, const float* s) {
#pragma unroll
        for (int t = 0; t < 2; t++) {
            int i = tid + t * 256;
            int r = i >> 2, q = i & 3;
            uint32_t sa = sbase + st * STAGE + (uint32_t)(r * ROWB + q * 16);
            const float* b = s + t * 8;
            __half2 h0 = __floats2half2_rn(b[0], b[1]);
            __half2 h1 = __floats2half2_rn(b[2], b[3]);
            __half2 h2 = __floats2half2_rn(b[4], b[5]);
            __half2 h3 = __floats2half2_rn(b[6], b[7]);
            STS128(sa, *reinterpret_cast<uint32_t*>(&h0), *reinterpret_cast<uint32_t*>(&h1),
                       *reinterpret_cast<uint32_t*>(&h2), *reinterpret_cast<uint32_t*>(&h3));
        }
    };

    if constexpr (CONV) ldg_A(0, abuf[0]);
    else load_A_async(0, 0);
    load_W(0, 0);
    CP_COMMIT();

    for (int kc = 0; kc < NIT; kc++) {
        if (kc + 1 < NIT) {
            if constexpr (CONV) ldg_A(kc + 1, abuf[(kc + 1) & 1]);
            else load_A_async(kc + 1, (kc + 1) & 1);
            load_W(kc + 1, (kc + 1) & 1);
            CP_COMMIT();
            CP_WAIT1();
        } else {
            CP_WAIT0();
        }
        if constexpr (CONV) sts_A(kc & 1, abuf[kc & 1]);
        __syncthreads();

        uint32_t stoff = (uint32_t)((kc & 1) * STAGE);
#pragma unroll
        for (int ks = 0; ks < 2; ks++) {
            uint32_t ah[4][4], bh[4][2];
#pragma unroll
            for (int mt = 0; mt < 4; mt++) {
                uint32_t addr = sbase + stoff +
                    (uint32_t)((m0w + mt * 16 + (lane & 15)) * ROWB + (ks * 2 + (lane >> 4)) * 16);
                LDSM_X4(ah[mt], addr);
            }
#pragma unroll
            for (int nt = 0; nt < 4; nt++) {
                uint32_t addr = sbase + stoff + TILE +
                    (uint32_t)((n0w + nt * 8 + (lane & 7)) * ROWB + (ks * 2 + ((lane >> 3) & 1)) * 16);
                LDSM_X2(bh[nt], addr);
            }
#pragma unroll
            for (int mt = 0; mt < 4; mt++)
#pragma unroll
                for (int nt = 0; nt < 4; nt++)
                    mma_f16(acc[mt][nt], ah[mt], bh[nt]);
        }
        __syncthreads();
    }

#pragma unroll
    for (int mt = 0; mt < 4; mt++) {
        int rlo = row0 + m0w + mt * 16 + (lane >> 2);
        int rhi = rlo + 8;
#pragma unroll
        for (int nt = 0; nt < 4; nt++) {
            int gn = n0 + n0w + nt * 8 + (lane & 3) * 2;
            bool isg = gn < NHALF;
            int col = isg ? gn : gn - NHALF;
            if (isg) {
                if (rlo < nrows)
                    *reinterpret_cast<__half2*>(out_gcn + (size_t)rlo * NHALF + col) =
                        __floats2half2_rn(acc[mt][nt][0], acc[mt][nt][1]);
                if (rhi < nrows)
                    *reinterpret_cast<__half2*>(out_gcn + (size_t)rhi * NHALF + col) =
                        __floats2half2_rn(acc[mt][nt][2], acc[mt][nt][3]);
            } else {
                float bx = __ldg(&bias[col]), by = __ldg(&bias[col + 1]);
                if (rlo < nrows)
                    *reinterpret_cast<__half2*>(out_self + (size_t)rlo * NHALF + col) =
                        __floats2half2_rn(acc[mt][nt][0] + bx, acc[mt][nt][1] + by);
                if (rhi < nrows)
                    *reinterpret_cast<__half2*>(out_self + (size_t)rhi * NHALF + col) =
                        __floats2half2_rn(acc[mt][nt][2] + bx, acc[mt][nt][3] + by);
            }
        }
    }
}

// ================= CSR aggregation + BN fused (packed edges, 4x unrolled) =================
__global__ void __launch_bounds__(256) agg_bn12_kernel(
    const __half* __restrict__ hw, const __half* __restrict__ selfacc,
    const float* __restrict__ gamma, const float* __restrict__ beta,
    const float* __restrict__ mean, const float* __restrict__ var,
    __half* __restrict__ hout)
{
    int v = (blockIdx.x * blockDim.x + threadIdx.x) >> 5;
    if (v >= NN) return;
    int lane = threadIdx.x & 31;
    int beg = g_rowptr[v], end = g_rowptr[v + 1];

    float4 acc = make_float4(0.f, 0.f, 0.f, 0.f);
    int e = beg;
    for (; e + 3 < end; e += 4) {
        uint2 er[4];
        uint2 u[4];
#pragma unroll
        for (int q = 0; q < 4; q++) er[q] = __ldg(&g_edge[e + q]);
#pragma unroll
        for (int q = 0; q < 4; q++)
            u[q] = __ldg(reinterpret_cast<const uint2*>(hw + (size_t)er[q].x * 128) + lane);
#pragma unroll
        for (int q = 0; q < 4; q++) {
            float w = __uint_as_float(er[q].y);
            float2 a = __half22float2(*reinterpret_cast<__half2*>(&u[q].x));
            float2 b = __half22float2(*reinterpret_cast<__half2*>(&u[q].y));
            acc.x += w * a.x;
            acc.y += w * a.y;
            acc.z += w * b.x;
            acc.w += w * b.y;
        }
    }
    for (; e < end; e++) {
        uint2 e0 = __ldg(&g_edge[e]);
        float w0 = __uint_as_float(e0.y);
        uint2 u0 = __ldg(reinterpret_cast<const uint2*>(hw + (size_t)e0.x * 128) + lane);
        float2 a0 = __half22float2(*reinterpret_cast<__half2*>(&u0.x));
        float2 b0 = __half22float2(*reinterpret_cast<__half2*>(&u0.y));
        acc.x += w0 * a0.x; acc.y += w0 * a0.y; acc.z += w0 * b0.x; acc.w += w0 * b0.y;
    }

    uint2 su = __ldg(reinterpret_cast<const uint2*>(selfacc + (size_t)v * 128) + lane);
    float2 s0 = __half22float2(*reinterpret_cast<__half2*>(&su.x));
    float2 s1 = __half22float2(*reinterpret_cast<__half2*>(&su.y));
    int c = lane * 4;
    float vals[4] = { acc.x + s0.x, acc.y + s0.y, acc.z + s1.x, acc.w + s1.y };
#pragma unroll
    for (int j = 0; j < 4; j++) {
        int ch = c + j;
        float t = vals[j];
        t = (t - __ldg(&mean[ch])) * rsqrtf(__ldg(&var[ch]) + EPSBN) * __ldg(&gamma[ch]) + __ldg(&beta[ch]);
        vals[j] = fmaxf(t, 0.f);
    }
    __half2 p0 = __floats2half2_rn(vals[0], vals[1]);
    __half2 p1 = __floats2half2_rn(vals[2], vals[3]);
    uint2 pk;
    pk.x = *reinterpret_cast<uint32_t*>(&p0);
    pk.y = *reinterpret_cast<uint32_t*>(&p1);
    *reinterpret_cast<uint2*>(hout + (size_t)v * 128 + c) = pk;
}

__global__ void __launch_bounds__(256) agg_bn3_kernel(
    const __half* __restrict__ hw, const __half* __restrict__ selfacc,
    const float* __restrict__ gamma, const float* __restrict__ beta,
    const float* __restrict__ mean, const float* __restrict__ var,
    float* __restrict__ out)
{
    int v = (blockIdx.x * blockDim.x + threadIdx.x) >> 5;
    if (v >= NN) return;
    int lane = threadIdx.x & 31;
    if (lane >= 20) return;
    int beg = g_rowptr[v], end = g_rowptr[v + 1];

    float2 acc = make_float2(0.f, 0.f);
    int e = beg;
    for (; e + 3 < end; e += 4) {
        uint2 e0 = __ldg(&g_edge[e]);
        uint2 e1 = __ldg(&g_edge[e + 1]);
        uint2 e2 = __ldg(&g_edge[e + 2]);
        uint2 e3 = __ldg(&g_edge[e + 3]);
        uint u0 = __ldg(reinterpret_cast<const uint32_t*>(hw + (size_t)e0.x * NCLS_PAD) + lane);
        uint u1 = __ldg(reinterpret_cast<const uint32_t*>(hw + (size_t)e1.x * NCLS_PAD) + lane);
        uint u2 = __ldg(reinterpret_cast<const uint32_t*>(hw + (size_t)e2.x * NCLS_PAD) + lane);
        uint u3 = __ldg(reinterpret_cast<const uint32_t*>(hw + (size_t)e3.x * NCLS_PAD) + lane);
        float2 f0 = __half22float2(*reinterpret_cast<__half2*>(&u0));
        float2 f1 = __half22float2(*reinterpret_cast<__half2*>(&u1));
        float2 f2 = __half22float2(*reinterpret_cast<__half2*>(&u2));
        float2 f3 = __half22float2(*reinterpret_cast<__half2*>(&u3));
        float w0 = __uint_as_float(e0.y), w1 = __uint_as_float(e1.y);
        float w2 = __uint_as_float(e2.y), w3 = __uint_as_float(e3.y);
        acc.x += w0 * f0.x + w1 * f1.x + w2 * f2.x + w3 * f3.x;
        acc.y += w0 * f0.y + w1 * f1.y + w2 * f2.y + w3 * f3.y;
    }
    for (; e < end; e++) {
        uint2 e0 = __ldg(&g_edge[e]);
        float w0 = __uint_as_float(e0.y);
        uint u0 = __ldg(reinterpret_cast<const uint32_t*>(hw + (size_t)e0.x * NCLS_PAD) + lane);
        float2 f0 = __half22float2(*reinterpret_cast<__half2*>(&u0));
        acc.x += w0 * f0.x;
        acc.y += w0 * f0.y;
    }

    uint su = __ldg(reinterpret_cast<const uint32_t*>(selfacc + (size_t)v * NCLS_PAD) + lane);
    float2 sf = __half22float2(*reinterpret_cast<__half2*>(&su));
    int c = lane * 2;
    float2 o;
    o.x = (acc.x + sf.x - __ldg(&mean[c]))     * rsqrtf(__ldg(&var[c]) + EPSBN)     * __ldg(&gamma[c])     + __ldg(&beta[c]);
    o.y = (acc.y + sf.y - __ldg(&mean[c + 1])) * rsqrtf(__ldg(&var[c + 1]) + EPSBN) * __ldg(&gamma[c + 1]) + __ldg(&beta[c + 1]);
    *reinterpret_cast<float2*>(out + (size_t)v * NCLS + c) = o;
}

// ================= launch =================
extern "C" void kernel_launch(void* const* d_in, const int* in_sizes, int n_in,
                              void* d_out, int out_size) {
    const float* x   = (const float*)d_in[0];
    const int*   ei  = (const int*)d_in[1];
    const float* ew  = (const float*)d_in[2];
    const int* src = ei;
    const int* dst = ei + EE;

    const float* wg1 = (const float*)d_in[3];
    const float* ws1 = (const float*)d_in[4];
    const float* b1  = (const float*)d_in[5];
    const float* gm1 = (const float*)d_in[6];
    const float* bt1 = (const float*)d_in[7];
    const float* mn1 = (const float*)d_in[8];
    const float* vr1 = (const float*)d_in[9];

    const float* wg2 = (const float*)d_in[10];
    const float* ws2 = (const float*)d_in[11];
    const float* b2  = (const float*)d_in[12];
    const float* gm2 = (const float*)d_in[13];
    const float* bt2 = (const float*)d_in[14];
    const float* mn2 = (const float*)d_in[15];
    const float* vr2 = (const float*)d_in[16];

    const float* wg3 = (const float*)d_in[17];
    const float* ws3 = (const float*)d_in[18];
    const float* b3  = (const float*)d_in[19];
    const float* gm3 = (const float*)d_in[20];
    const float* bt3 = (const float*)d_in[21];
    const float* mn3 = (const float*)d_in[22];
    const float* vr3 = (const float*)d_in[23];

    float* out = (float*)d_out;

    float* p_b3p;
    __half *p_hwh, *p_acch, *p_hh, *p_w1h, *p_w2h, *p_w3h;
    cudaGetSymbolAddress((void**)&p_hwh,  g_hwh);
    cudaGetSymbolAddress((void**)&p_acch, g_acch);
    cudaGetSymbolAddress((void**)&p_b3p,  g_b3p);
    cudaGetSymbolAddress((void**)&p_hh,   g_hh);
    cudaGetSymbolAddress((void**)&p_w1h,  g_w1h);
    cudaGetSymbolAddress((void**)&p_w2h,  g_w2h);
    cudaGetSymbolAddress((void**)&p_w3h,  g_w3h);

    const int GSMEM = 2 * 2 * 128 * 80;  // 40960 bytes

    static cudaStream_t s2 = nullptr;
    static cudaEvent_t ev_fork = nullptr, ev_join = nullptr, ev_join2 = nullptr;
    if (s2 == nullptr) {
        cudaStreamCreateWithFlags(&s2, cudaStreamNonBlocking);
        cudaEventCreateWithFlags(&ev_fork, cudaEventDisableTiming);
        cudaEventCreateWithFlags(&ev_join, cudaEventDisableTiming);
        cudaEventCreateWithFlags(&ev_join2, cudaEventDisableTiming);
    }

    const int TPB = 256;
    const int GRID_M = (NN + 127) / 128;           // 391
    const int GRID_W = (NN * 32 + TPB - 1) / TPB;

    // ---- fork: CSR build chain on side stream; weight prep after join1 ----
    cudaEventRecord(ev_fork, 0);
    cudaStreamWaitEvent(s2, ev_fork, 0);
    zero_dc_kernel<<<(NN + TPB - 1) / TPB, TPB, 0, s2>>>();
    count_deg_kernel<<<(EE + TPB - 1) / TPB, TPB, 0, s2>>>(dst, ew, EE);
    blocksum_dinv_kernel<<<NBLK, SCAN_B, 0, s2>>>();
    scatter_rowptr_kernel<<<NBLK, SCAN_B, 0, s2>>>();
    fill_kernel<<<(EE + TPB - 1) / TPB, TPB, 0, s2>>>(src, dst, ew, EE);
    cudaEventRecord(ev_join, s2);   // CSR ready (gates agg_bn1)
    prep_w_kernel<<<(2 * 128 * 128 + TPB - 1) / TPB, TPB, 0, s2>>>(wg2, ws2, 128, 128, 128, p_w2h);
    prep_w_kernel<<<(2 * 64 * 128 + TPB - 1) / TPB, TPB, 0, s2>>>(wg3, ws3, 128, 40, 64, p_w3h);
    prep_b3_kernel<<<1, 64, 0, s2>>>(b3);
    cudaEventRecord(ev_join2, s2);  // weights ready (gates gemm2/3)

    // ---- main stream: layer-1 GEMM with fused fp32->fp16 A conversion ----
    prep_w_kernel<<<(2 * 128 * 256 + TPB - 1) / TPB, TPB>>>(wg1, ws1, 256, 128, 128, p_w1h);
    gcn_gemm_mma<256, 128, true><<<dim3(GRID_M, 2), 256, GSMEM>>>(x, p_w1h, b1, p_hwh, p_acch, NN);

    // ---- join 1: aggregation needs CSR ----
    cudaStreamWaitEvent(0, ev_join, 0);
    agg_bn12_kernel<<<GRID_W, TPB>>>(p_hwh, p_acch, gm1, bt1, mn1, vr1, p_hh);

    // ---- join 2 + layer 2 ----
    cudaStreamWaitEvent(0, ev_join2, 0);
    gcn_gemm_mma<128, 128, false><<<dim3(GRID_M, 2), 256, GSMEM>>>(p_hh, p_w2h, b2, p_hwh, p_acch, NN);
    agg_bn12_kernel<<<GRID_W, TPB>>>(p_hwh, p_acch, gm2, bt2, mn2, vr2, p_hh);

    // ---- layer 3 ----
    gcn_gemm_mma<128, 64, false><<<dim3(GRID_M, 1), 256, GSMEM>>>(p_hh, p_w3h, p_b3p, p_hwh, p_acch, NN);
    agg_bn3_kernel<<<GRID_W, TPB>>>(p_hwh, p_acch, gm3, bt3, mn3, vr3, out);
}